// round 2
// baseline (speedup 1.0000x reference)
#include <cuda_runtime.h>

#define NB_   4
#define BATCH 8
#define LEN   4096
#define FREQ  80
#define DIM   512
#define HID   2048
#define USEQ  1024
#define C1    128
#define C2    256
#define C3    512
#define H1    2048
#define W1    40
#define H2    1024
#define W2    20
#define MCONV (BATCH*H2*W2)      /* 163840 */
#define K2C   (9*C1)             /* 1152 */
#define K3C   (9*C2)             /* 2304 */
#define KE    (C3*W2)            /* 10240 */
#define MT    (BATCH*USEQ)       /* 8192 */
#define HTOK  (MT*DIM)           /* 4194304 */

// ---------------- scratch (device globals; no allocations) ----------------
__device__ float g_conv1[BATCH*H1*W1*C1];   // (b,h,w,c) channel-last
__device__ float g_col2[MCONV*K2C];
__device__ float g_c2[MCONV*C2];            // (b,h,w,c)
__device__ float g_col3[MCONV*K3C];
__device__ float g_c3[MCONV*C3];            // (b,u,w,c)
__device__ float g_yr[MT*KE];
__device__ float g_t0[HTOK];
__device__ float g_h[HTOK];
__device__ float g_xn[HTOK];
__device__ float g_xk[HTOK];
__device__ float g_xv[HTOK];
__device__ float g_xr[HTOK];
__device__ float g_k[HTOK];
__device__ float g_v[HTOK];
__device__ float g_r[HTOK];
__device__ float g_rwkv[HTOK];
__device__ float g_kk[MT*HID];
__device__ float g_w2r[K2C*C2];
__device__ float g_w3r[K3C*C3];

// ---------------- conv1: direct, (B,1,4096,80) -> (B,2048,40,128) ----------
__global__ void conv1_k(const float* __restrict__ x, const float* __restrict__ w,
                        const float* __restrict__ bias){
  int t = blockIdx.x*256 + threadIdx.x;
  int co = t & 127;
  int rest = t >> 7;
  int wo = rest % W1; rest /= W1;
  int ho = rest % H1; int b = rest / H1;
  float acc = bias[co];
  int hi0 = 2*ho - 1, wi0 = 2*wo - 1;
  #pragma unroll
  for(int kh=0; kh<3; kh++){
    int hi = hi0 + kh;
    if(hi < 0 || hi >= LEN) continue;
    #pragma unroll
    for(int kw=0; kw<3; kw++){
      int wi = wi0 + kw;
      if(wi < 0 || wi >= FREQ) continue;
      acc = fmaf(x[(hi + (long)b*LEN)*FREQ + wi], w[co*9 + kh*3 + kw], acc);
    }
  }
  g_conv1[t] = fmaxf(acc, 0.f);
}

// ---------------- weight reorders: OIHW -> [(kh*3+kw)*CI+ci][co] ------------
__global__ void reorder_w2(const float* __restrict__ w){
  int t = blockIdx.x*256 + threadIdx.x;
  if(t >= C2*C1*9) return;
  int co = t / (C1*9); int rem = t % (C1*9);
  int ci = rem / 9;    int r  = rem % 9;
  g_w2r[(r*C1 + ci)*C2 + co] = w[t];
}
__global__ void reorder_w3(const float* __restrict__ w){
  int t = blockIdx.x*256 + threadIdx.x;
  if(t >= C3*C2*9) return;
  int co = t / (C2*9); int rem = t % (C2*9);
  int ci = rem / 9;    int r  = rem % 9;
  g_w3r[(r*C2 + ci)*C3 + co] = w[t];
}

// ---------------- im2col ----------------------------------------------------
__global__ void im2col2_k(){
  int t = blockIdx.x*256 + threadIdx.x;          // m*K2C + k
  int k = t % K2C; int m = t / K2C;
  int r = k >> 7; int ci = k & 127;
  int kh = r / 3, kw = r % 3;
  int wo = m % W2; int rest = m / W2;
  int ho = rest % H2; int b = rest / H2;
  int hi = 2*ho + kh - 1, wi = 2*wo + kw - 1;
  float v = 0.f;
  if(hi >= 0 && hi < H1 && wi >= 0 && wi < W1)
    v = g_conv1[((b*H1 + hi)*W1 + wi)*C1 + ci];
  g_col2[t] = v;
}
__global__ void im2col3_k(){
  int t = blockIdx.x*256 + threadIdx.x;
  int k = t % K3C; int m = t / K3C;
  int r = k >> 8; int ci = k & 255;
  int kh = r / 3, kw = r % 3;
  int wo = m % W2; int rest = m / W2;
  int ho = rest % H2; int b = rest / H2;
  int hi = ho + kh - 1, wi = wo + kw - 1;
  float v = 0.f;
  if(hi >= 0 && hi < H2 && wi >= 0 && wi < W2)
    v = g_c2[((b*H2 + hi)*W2 + wi)*C2 + ci];
  g_col3[t] = v;
}

// ---------------- generic fp32 SGEMM, 128x128x8, 8x8 microtile --------------
// C[M,N] = epi(act(A[M,K] @ W[K,N] + bias))
// ACT: 0 none, 1 relu, 2 sigmoid, 3 relu^2
// EPI: 0 store, 1 C += acc (residual), 2 C += mul*acc
template<int ACT, int EPI>
__global__ void sgemm_k(int M, int N, int K,
                        const float* __restrict__ A, const float* __restrict__ W,
                        const float* __restrict__ bias, float* __restrict__ C,
                        const float* __restrict__ mul){
  __shared__ float As[8][128];
  __shared__ float Bs[8][128];
  int bm = blockIdx.y, bn = blockIdx.x;
  int tid = threadIdx.x;
  int tr = tid >> 4, tc = tid & 15;
  const float* Ab = A + (long)bm*128*K;
  const float* Wb = W + bn*128;
  float acc[8][8];
  #pragma unroll
  for(int i=0;i<8;i++)
    #pragma unroll
    for(int j=0;j<8;j++) acc[i][j] = 0.f;

  int aRow = tid >> 1, aCol = (tid & 1)*4;
  int bRow = tid >> 5, bCol = (tid & 31)*4;

  for(int k0=0; k0<K; k0+=8){
    float4 av = *(const float4*)(Ab + (long)aRow*K + k0 + aCol);
    float4 bv = *(const float4*)(Wb + (long)(k0 + bRow)*N + bCol);
    __syncthreads();
    As[aCol+0][aRow] = av.x; As[aCol+1][aRow] = av.y;
    As[aCol+2][aRow] = av.z; As[aCol+3][aRow] = av.w;
    *(float4*)&Bs[bRow][bCol] = bv;
    __syncthreads();
    #pragma unroll
    for(int kk=0; kk<8; kk++){
      float ar[8], br[8];
      *(float4*)(ar)   = *(const float4*)&As[kk][tr*8];
      *(float4*)(ar+4) = *(const float4*)&As[kk][tr*8+4];
      *(float4*)(br)   = *(const float4*)&Bs[kk][tc*8];
      *(float4*)(br+4) = *(const float4*)&Bs[kk][tc*8+4];
      #pragma unroll
      for(int i=0;i<8;i++)
        #pragma unroll
        for(int j=0;j<8;j++)
          acc[i][j] = fmaf(ar[i], br[j], acc[i][j]);
    }
  }

  int col0 = bn*128 + tc*8;
  #pragma unroll
  for(int i=0;i<8;i++){
    long row = (long)bm*128 + tr*8 + i;
    float* cp = C + row*N + col0;
    float r8[8];
    #pragma unroll
    for(int j=0;j<8;j++){
      float vv = acc[i][j];
      if(bias) vv += bias[col0 + j];
      if(ACT == 1)      vv = fmaxf(vv, 0.f);
      else if(ACT == 2) vv = 1.f/(1.f + __expf(-vv));
      else if(ACT == 3){ vv = fmaxf(vv, 0.f); vv = vv*vv; }
      r8[j] = vv;
    }
    if(EPI == 1){
      #pragma unroll
      for(int j=0;j<8;j++) r8[j] += cp[j];
    } else if(EPI == 2){
      const float* mp = mul + row*N + col0;
      #pragma unroll
      for(int j=0;j<8;j++) r8[j] = cp[j] + mp[j]*r8[j];
    }
    *(float4*)cp     = make_float4(r8[0], r8[1], r8[2], r8[3]);
    *(float4*)(cp+4) = make_float4(r8[4], r8[5], r8[6], r8[7]);
  }
}

// ---------------- reshape (b,u,w,c) -> (b,u, c*20+w) -------------------------
__global__ void reshape_k(){
  __shared__ float sm[KE];
  int m = blockIdx.x;
  const float* src = g_c3 + (long)m*KE;   // contiguous: idx = w*512 + c
  for(int i=threadIdx.x; i<KE; i+=256){
    int w = i / 512, c = i & 511;
    sm[c*W2 + w] = src[i];
  }
  __syncthreads();
  float* dst = g_yr + (long)m*KE;
  for(int i=threadIdx.x; i<KE; i+=256) dst[i] = sm[i];
}

// ---------------- LayerNorm over D=512, one block (128 thr) per token --------
__global__ void ln_k(const float* __restrict__ x, const float* __restrict__ gw,
                     const float* __restrict__ gb, float* __restrict__ o){
  int m = blockIdx.x;
  int tid = threadIdx.x;
  const float* xr = x + (long)m*DIM;
  float v[4]; float s = 0.f, sq = 0.f;
  #pragma unroll
  for(int j=0;j<4;j++){ float t = xr[tid + j*128]; v[j] = t; s += t; sq += t*t; }
  #pragma unroll
  for(int off=16; off; off>>=1){
    s  += __shfl_xor_sync(0xffffffffu, s,  off);
    sq += __shfl_xor_sync(0xffffffffu, sq, off);
  }
  __shared__ float ss[4], sqs[4];
  if((tid & 31) == 0){ ss[tid>>5] = s; sqs[tid>>5] = sq; }
  __syncthreads();
  s  = (ss[0]+ss[1]) + (ss[2]+ss[3]);
  sq = (sqs[0]+sqs[1]) + (sqs[2]+sqs[3]);
  float mean = s * (1.f/DIM);
  float var  = sq * (1.f/DIM) - mean*mean;
  float rstd = rsqrtf(var + 1e-5f);
  float* orow = o + (long)m*DIM;
  #pragma unroll
  for(int j=0;j<4;j++){
    int d = tid + j*128;
    orow[d] = (v[j] - mean)*rstd*gw[d] + gb[d];
  }
}

// ---------------- time-shift mixes -------------------------------------------
__global__ void mix3_k(const float* __restrict__ xn, const float* __restrict__ mk,
                       const float* __restrict__ mv, const float* __restrict__ mr){
  int t = blockIdx.x*256 + threadIdx.x;
  int d = t & (DIM-1);
  int tok = (t >> 9) & (USEQ-1);
  float cur = xn[t];
  float sh = tok ? xn[t - DIM] : 0.f;
  float dcs = cur - sh;
  g_xk[t] = fmaf(dcs, mk[d], sh);
  g_xv[t] = fmaf(dcs, mv[d], sh);
  g_xr[t] = fmaf(dcs, mr[d], sh);
}
__global__ void mix2_k(const float* __restrict__ xn, const float* __restrict__ mk,
                       const float* __restrict__ mr){
  int t = blockIdx.x*256 + threadIdx.x;
  int d = t & (DIM-1);
  int tok = (t >> 9) & (USEQ-1);
  float cur = xn[t];
  float sh = tok ? xn[t - DIM] : 0.f;
  float dcs = cur - sh;
  g_xk[t] = fmaf(dcs, mk[d], sh);
  g_xr[t] = fmaf(dcs, mr[d], sh);
}

// ---------------- WKV scan (fused with r gating): out = r * wkv --------------
__global__ void wkv_k(const float* __restrict__ k, const float* __restrict__ v,
                      const float* __restrict__ r,
                      const float* __restrict__ dec, const float* __restrict__ fir,
                      float* __restrict__ out){
  int t = blockIdx.x*blockDim.x + threadIdx.x;   // 4096 threads (b,d)
  int d = t & (DIM-1); int b = t >> 9;
  float w = -__expf(dec[d]);
  float u = fir[d];
  float aa = 0.f, bb = 0.f, pp = -1e38f;
  long base = (long)b*USEQ*DIM + d;
  const float* kp = k + base;
  const float* vp = v + base;
  const float* rp = r + base;
  float* op = out + base;
  for(int tt=0; tt<USEQ; tt++){
    long off = (long)tt*DIM;
    float kt = kp[off], vt = vp[off];
    float ww = u + kt;
    float p  = fmaxf(pp, ww);
    float e1 = __expf(pp - p), e2 = __expf(ww - p);
    float o  = (e1*aa + e2*vt) / (e1*bb + e2);
    op[off]  = rp[off] * o;
    float ww2 = pp + w;
    float p2  = fmaxf(ww2, kt);
    e1 = __expf(ww2 - p2); e2 = __expf(kt - p2);
    aa = e1*aa + e2*vt; bb = e1*bb + e2; pp = p2;
  }
}

// ---------------- olens tail --------------------------------------------------
__global__ void tail_k(const int* __restrict__ x_len, float* __restrict__ out, int out_size){
  int b = threadIdx.x;
  if(b < BATCH && out_size >= HTOK + BATCH){
    int l1 = (x_len[b] - 1)/2 + 1;
    int ol = (l1 - 1)/2 + 1;
    out[HTOK + b] = (float)ol;
  }
}

// ---------------- host side ---------------------------------------------------
template <typename T>
static float* symaddr(const T& s){ void* p = nullptr; cudaGetSymbolAddress(&p, s); return (float*)p; }

template<int ACT, int EPI>
static void gemm(int M, int N, int K, const float* A, const float* W,
                 const float* bias, float* C, const float* mul){
  dim3 grid(N/128, M/128);
  sgemm_k<ACT,EPI><<<grid, 256>>>(M, N, K, A, W, bias, C, mul);
}

extern "C" void kernel_launch(void* const* d_in, const int* in_sizes, int n_in,
                              void* d_out, int out_size){
  const float* x       = (const float*)d_in[0];
  const int*   x_len   = (const int*)  d_in[1];
  const float* conv1_w = (const float*)d_in[2];
  const float* conv1_b = (const float*)d_in[3];
  const float* conv2_w = (const float*)d_in[4];
  const float* conv2_b = (const float*)d_in[5];
  const float* conv3_w = (const float*)d_in[6];
  const float* conv3_b = (const float*)d_in[7];
  const float* embed_w = (const float*)d_in[8];
  const float* embed_b = (const float*)d_in[9];
  const float* eln_g   = (const float*)d_in[10];
  const float* eln_b   = (const float*)d_in[11];
  const float* lag     = (const float*)d_in[12];
  const float* lab     = (const float*)d_in[13];
  const float* dec     = (const float*)d_in[14];
  const float* fir     = (const float*)d_in[15];
  const float* amk     = (const float*)d_in[16];
  const float* amv     = (const float*)d_in[17];
  const float* amr     = (const float*)d_in[18];
  const float* awk     = (const float*)d_in[19];
  const float* awv     = (const float*)d_in[20];
  const float* awr     = (const float*)d_in[21];
  const float* awo     = (const float*)d_in[22];
  const float* lfg     = (const float*)d_in[23];
  const float* lfb     = (const float*)d_in[24];
  const float* fmk     = (const float*)d_in[25];
  const float* fmr     = (const float*)d_in[26];
  const float* fwk     = (const float*)d_in[27];
  const float* fwv     = (const float*)d_in[28];
  const float* fwr     = (const float*)d_in[29];
  const float* flg     = (const float*)d_in[30];
  const float* flb     = (const float*)d_in[31];
  float* out = (float*)d_out;

  float* p_col2 = symaddr(g_col2);
  float* p_c2   = symaddr(g_c2);
  float* p_col3 = symaddr(g_col3);
  float* p_c3   = symaddr(g_c3);
  float* p_yr   = symaddr(g_yr);
  float* p_t0   = symaddr(g_t0);
  float* p_h    = symaddr(g_h);
  float* p_xn   = symaddr(g_xn);
  float* p_xk   = symaddr(g_xk);
  float* p_xv   = symaddr(g_xv);
  float* p_xr   = symaddr(g_xr);
  float* p_k    = symaddr(g_k);
  float* p_v    = symaddr(g_v);
  float* p_r    = symaddr(g_r);
  float* p_rwkv = symaddr(g_rwkv);
  float* p_kk   = symaddr(g_kk);
  float* p_w2r  = symaddr(g_w2r);
  float* p_w3r  = symaddr(g_w3r);

  // conv frontend
  conv1_k<<<(BATCH*H1*W1*C1)/256, 256>>>(x, conv1_w, conv1_b);
  reorder_w2<<<(C2*C1*9 + 255)/256, 256>>>(conv2_w);
  reorder_w3<<<(C3*C2*9 + 255)/256, 256>>>(conv3_w);
  im2col2_k<<<(MCONV*K2C)/256, 256>>>();
  gemm<1,0>(MCONV, C2, K2C, p_col2, p_w2r, conv2_b, p_c2, nullptr);
  im2col3_k<<<(MCONV*K3C)/256, 256>>>();
  gemm<1,0>(MCONV, C3, K3C, p_col3, p_w3r, conv3_b, p_c3, nullptr);
  reshape_k<<<MT, 256>>>();
  gemm<0,0>(MT, DIM, KE, p_yr, embed_w, embed_b, p_t0, nullptr);
  ln_k<<<MT, 128>>>(p_t0, eln_g, eln_b, p_h);

  // RWKV blocks
  for(int i=0; i<NB_; i++){
    long w2 = (long)i*DIM*DIM;
    // time mixing
    ln_k<<<MT, 128>>>(p_h, lag + i*DIM, lab + i*DIM, p_xn);
    mix3_k<<<HTOK/256, 256>>>(p_xn, amk + i*DIM, amv + i*DIM, amr + i*DIM);
    gemm<0,0>(MT, DIM, DIM, p_xk, awk + w2, nullptr, p_k, nullptr);
    gemm<0,0>(MT, DIM, DIM, p_xv, awv + w2, nullptr, p_v, nullptr);
    gemm<2,0>(MT, DIM, DIM, p_xr, awr + w2, nullptr, p_r, nullptr);
    wkv_k<<<(BATCH*DIM)/256, 256>>>(p_k, p_v, p_r, dec + i*DIM, fir + i*DIM, p_rwkv);
    gemm<0,1>(MT, DIM, DIM, p_rwkv, awo + w2, nullptr, p_h, nullptr);
    // channel mixing
    ln_k<<<MT, 128>>>(p_h, lfg + i*DIM, lfb + i*DIM, p_xn);
    mix2_k<<<HTOK/256, 256>>>(p_xn, fmk + i*DIM, fmr + i*DIM);
    gemm<3,0>(MT, HID, DIM, p_xk, fwk + (long)i*DIM*HID, nullptr, p_kk, nullptr);
    gemm<2,0>(MT, DIM, DIM, p_xr, fwr + w2, nullptr, p_r, nullptr);
    gemm<0,2>(MT, DIM, HID, p_kk, fwv + (long)i*HID*DIM, nullptr, p_h, p_r);
  }

  ln_k<<<MT, 128>>>(p_h, flg, flb, out);
  tail_k<<<1, 32>>>(x_len, out, out_size);
}

// round 3
// speedup vs baseline: 1.1694x; 1.1694x over previous
#include <cuda_runtime.h>

#define NB_   4
#define BATCH 8
#define LEN   4096
#define FREQ  80
#define DIM   512
#define HID   2048
#define USEQ  1024
#define C1    128
#define C2    256
#define C3    512
#define H1    2048
#define W1    40
#define H2    1024
#define W2    20
#define MCONV (BATCH*H2*W2)      /* 163840 */
#define K2C   (9*C1)             /* 1152 */
#define K3C   (9*C2)             /* 2304 */
#define KE    (C3*W2)            /* 10240 */
#define MT    (BATCH*USEQ)       /* 8192 */
#define HTOK  (MT*DIM)           /* 4194304 */

// ---------------- scratch (device globals; no allocations) ----------------
__device__ float g_conv1[BATCH*H1*W1*C1];   // (b,h,w,c) channel-last
__device__ float g_col2[MCONV*K2C];
__device__ float g_c2[MCONV*C2];            // (b,h,w,c)
__device__ float g_col3[MCONV*K3C];
__device__ float g_c3[MCONV*C3];            // (b,u,w,c)
__device__ float g_yr[MT*KE];
__device__ float g_t0[HTOK];
__device__ float g_h[HTOK];
__device__ float g_xn[HTOK];
__device__ float g_xk[HTOK];
__device__ float g_xv[HTOK];
__device__ float g_xr[HTOK];
__device__ float g_k[HTOK];
__device__ float g_v[HTOK];
__device__ float g_r[HTOK];
__device__ float g_rwkv[HTOK];
__device__ float g_kk[MT*HID];
__device__ float g_w2r[K2C*C2];
__device__ float g_w3r[K3C*C3];

// ---------------- conv1: direct, (B,1,4096,80) -> (B,2048,40,128) ----------
__global__ void conv1_k(const float* __restrict__ x, const float* __restrict__ w,
                        const float* __restrict__ bias){
  int t = blockIdx.x*256 + threadIdx.x;
  int co = t & 127;
  int rest = t >> 7;
  int wo = rest % W1; rest /= W1;
  int ho = rest % H1; int b = rest / H1;
  float acc = bias[co];
  int hi0 = 2*ho - 1, wi0 = 2*wo - 1;
  #pragma unroll
  for(int kh=0; kh<3; kh++){
    int hi = hi0 + kh;
    if(hi < 0 || hi >= LEN) continue;
    #pragma unroll
    for(int kw=0; kw<3; kw++){
      int wi = wi0 + kw;
      if(wi < 0 || wi >= FREQ) continue;
      acc = fmaf(x[(hi + (long)b*LEN)*FREQ + wi], w[co*9 + kh*3 + kw], acc);
    }
  }
  g_conv1[t] = fmaxf(acc, 0.f);
}

// ---------------- weight reorders: OIHW -> [(kh*3+kw)*CI+ci][co] ------------
__global__ void reorder_w2(const float* __restrict__ w){
  int t = blockIdx.x*256 + threadIdx.x;
  if(t >= C2*C1*9) return;
  int co = t / (C1*9); int rem = t % (C1*9);
  int ci = rem / 9;    int r  = rem % 9;
  g_w2r[(r*C1 + ci)*C2 + co] = w[t];
}
__global__ void reorder_w3(const float* __restrict__ w){
  int t = blockIdx.x*256 + threadIdx.x;
  if(t >= C3*C2*9) return;
  int co = t / (C2*9); int rem = t % (C2*9);
  int ci = rem / 9;    int r  = rem % 9;
  g_w3r[(r*C2 + ci)*C3 + co] = w[t];
}

// ---------------- im2col (float4 over channel dim) --------------------------
__global__ void im2col2_k(){
  int t = blockIdx.x*256 + threadIdx.x;          // m*(K2C/4) + k4
  int k4 = t % (K2C/4); int m = t / (K2C/4);
  int k = k4*4;
  int r = k >> 7; int ci = k & 127;
  int kh = r / 3, kw = r % 3;
  int wo = m % W2; int rest = m / W2;
  int ho = rest % H2; int b = rest / H2;
  int hi = 2*ho + kh - 1, wi = 2*wo + kw - 1;
  float4 v = make_float4(0.f,0.f,0.f,0.f);
  if(hi >= 0 && hi < H1 && wi >= 0 && wi < W1)
    v = *(const float4*)&g_conv1[((b*H1 + hi)*W1 + wi)*C1 + ci];
  *(float4*)&g_col2[(long)m*K2C + k] = v;
}
__global__ void im2col3_k(){
  int t = blockIdx.x*256 + threadIdx.x;
  int k4 = t % (K3C/4); int m = t / (K3C/4);
  int k = k4*4;
  int r = k >> 8; int ci = k & 255;
  int kh = r / 3, kw = r % 3;
  int wo = m % W2; int rest = m / W2;
  int ho = rest % H2; int b = rest / H2;
  int hi = ho + kh - 1, wi = wo + kw - 1;
  float4 v = make_float4(0.f,0.f,0.f,0.f);
  if(hi >= 0 && hi < H2 && wi >= 0 && wi < W2)
    v = *(const float4*)&g_c2[((b*H2 + hi)*W2 + wi)*C2 + ci];
  *(float4*)&g_col3[(long)m*K3C + k] = v;
}

// ---------------- packed f32x2 helpers ---------------------------------------
__device__ __forceinline__ unsigned long long pack2(float v){
  unsigned long long r;
  asm("mov.b64 %0, {%1, %1};" : "=l"(r) : "r"(__float_as_uint(v)));
  return r;
}
__device__ __forceinline__ void fma2(unsigned long long& d, unsigned long long a,
                                     unsigned long long b){
  asm("fma.rn.f32x2 %0, %1, %2, %0;" : "+l"(d) : "l"(a), "l"(b));
}
__device__ __forceinline__ void unpack2(unsigned long long v, float& lo, float& hi){
  unsigned int a, b;
  asm("mov.b64 {%0, %1}, %2;" : "=r"(a), "=r"(b) : "l"(v));
  lo = __uint_as_float(a); hi = __uint_as_float(b);
}

// ---------------- generic fp32 SGEMM, 128x128x8, 8x8 microtile, FFMA2 -------
// C[M,N] = epi(act(A[M,K] @ W[K,N] + bias))
// ACT: 0 none, 1 relu, 2 sigmoid, 3 relu^2
// EPI: 0 store, 1 C += acc (residual), 2 C += mul*acc
template<int ACT, int EPI>
__global__ void sgemm_k(int M, int N, int K,
                        const float* __restrict__ A, const float* __restrict__ W,
                        const float* __restrict__ bias, float* __restrict__ C,
                        const float* __restrict__ mul){
  __shared__ float As[8][128];
  __shared__ float Bs[8][128];
  int bm = blockIdx.y, bn = blockIdx.x;
  int tid = threadIdx.x;
  int tr = tid >> 4, tc = tid & 15;
  const float* Ab = A + (long)bm*128*K;
  const float* Wb = W + bn*128;
  // acc pairs: accp[p][j] packs rows (tr*8+2p, tr*8+2p+1), col tc*8+j
  unsigned long long accp[4][8];
  #pragma unroll
  for(int p=0;p<4;p++)
    #pragma unroll
    for(int j=0;j<8;j++) accp[p][j] = 0ull;

  int aRow = tid >> 1, aCol = (tid & 1)*4;
  int bRow = tid >> 5, bCol = (tid & 31)*4;

  for(int k0=0; k0<K; k0+=8){
    float4 av = *(const float4*)(Ab + (long)aRow*K + k0 + aCol);
    float4 bv = *(const float4*)(Wb + (long)(k0 + bRow)*N + bCol);
    __syncthreads();
    As[aCol+0][aRow] = av.x; As[aCol+1][aRow] = av.y;
    As[aCol+2][aRow] = av.z; As[aCol+3][aRow] = av.w;
    *(float4*)&Bs[bRow][bCol] = bv;
    __syncthreads();
    #pragma unroll
    for(int kk=0; kk<8; kk++){
      unsigned long long arp[4];
      const float* arow = &As[kk][tr*8];
      #pragma unroll
      for(int p=0;p<4;p++) arp[p] = *(const unsigned long long*)(arow + 2*p);
      float br[8];
      *(float4*)(br)   = *(const float4*)&Bs[kk][tc*8];
      *(float4*)(br+4) = *(const float4*)&Bs[kk][tc*8+4];
      unsigned long long brp[8];
      #pragma unroll
      for(int j=0;j<8;j++) brp[j] = pack2(br[j]);
      #pragma unroll
      for(int p=0;p<4;p++)
        #pragma unroll
        for(int j=0;j<8;j++)
          fma2(accp[p][j], arp[p], brp[j]);
    }
  }

  int col0 = bn*128 + tc*8;
  #pragma unroll
  for(int p=0;p<4;p++){
    float lo[8], hi[8];
    #pragma unroll
    for(int j=0;j<8;j++) unpack2(accp[p][j], lo[j], hi[j]);
    #pragma unroll
    for(int half=0; half<2; half++){
      float* r8 = half ? hi : lo;
      long row = (long)bm*128 + tr*8 + 2*p + half;
      float* cp = C + row*N + col0;
      #pragma unroll
      for(int j=0;j<8;j++){
        float vv = r8[j];
        if(bias) vv += bias[col0 + j];
        if(ACT == 1)      vv = fmaxf(vv, 0.f);
        else if(ACT == 2) vv = 1.f/(1.f + __expf(-vv));
        else if(ACT == 3){ vv = fmaxf(vv, 0.f); vv = vv*vv; }
        r8[j] = vv;
      }
      if(EPI == 1){
        #pragma unroll
        for(int j=0;j<8;j++) r8[j] += cp[j];
      } else if(EPI == 2){
        const float* mp = mul + row*N + col0;
        #pragma unroll
        for(int j=0;j<8;j++) r8[j] = cp[j] + mp[j]*r8[j];
      }
      *(float4*)cp     = make_float4(r8[0], r8[1], r8[2], r8[3]);
      *(float4*)(cp+4) = make_float4(r8[4], r8[5], r8[6], r8[7]);
    }
  }
}

// ---------------- reshape (b,u,w,c) -> (b,u, c*20+w) -------------------------
__global__ void reshape_k(){
  __shared__ float sm[KE];
  int m = blockIdx.x;
  const float* src = g_c3 + (long)m*KE;   // contiguous: idx = w*512 + c
  for(int i=threadIdx.x; i<KE; i+=256){
    int w = i / 512, c = i & 511;
    sm[c*W2 + w] = src[i];
  }
  __syncthreads();
  float* dst = g_yr + (long)m*KE;
  for(int i=threadIdx.x; i<KE; i+=256) dst[i] = sm[i];
}

// ---------------- LayerNorm over D=512, one block (128 thr) per token --------
__global__ void ln_k(const float* __restrict__ x, const float* __restrict__ gw,
                     const float* __restrict__ gb, float* __restrict__ o){
  int m = blockIdx.x;
  int tid = threadIdx.x;
  const float* xr = x + (long)m*DIM;
  float v[4]; float s = 0.f, sq = 0.f;
  #pragma unroll
  for(int j=0;j<4;j++){ float t = xr[tid + j*128]; v[j] = t; s += t; sq += t*t; }
  #pragma unroll
  for(int off=16; off; off>>=1){
    s  += __shfl_xor_sync(0xffffffffu, s,  off);
    sq += __shfl_xor_sync(0xffffffffu, sq, off);
  }
  __shared__ float ss[4], sqs[4];
  if((tid & 31) == 0){ ss[tid>>5] = s; sqs[tid>>5] = sq; }
  __syncthreads();
  s  = (ss[0]+ss[1]) + (ss[2]+ss[3]);
  sq = (sqs[0]+sqs[1]) + (sqs[2]+sqs[3]);
  float mean = s * (1.f/DIM);
  float var  = sq * (1.f/DIM) - mean*mean;
  float rstd = rsqrtf(var + 1e-5f);
  float* orow = o + (long)m*DIM;
  #pragma unroll
  for(int j=0;j<4;j++){
    int d = tid + j*128;
    orow[d] = (v[j] - mean)*rstd*gw[d] + gb[d];
  }
}

// ---------------- time-shift mixes -------------------------------------------
__global__ void mix3_k(const float* __restrict__ xn, const float* __restrict__ mk,
                       const float* __restrict__ mv, const float* __restrict__ mr){
  int t = blockIdx.x*256 + threadIdx.x;
  int d = t & (DIM-1);
  int tok = (t >> 9) & (USEQ-1);
  float cur = xn[t];
  float sh = tok ? xn[t - DIM] : 0.f;
  float dcs = cur - sh;
  g_xk[t] = fmaf(dcs, mk[d], sh);
  g_xv[t] = fmaf(dcs, mv[d], sh);
  g_xr[t] = fmaf(dcs, mr[d], sh);
}
__global__ void mix2_k(const float* __restrict__ xn, const float* __restrict__ mk,
                       const float* __restrict__ mr){
  int t = blockIdx.x*256 + threadIdx.x;
  int d = t & (DIM-1);
  int tok = (t >> 9) & (USEQ-1);
  float cur = xn[t];
  float sh = tok ? xn[t - DIM] : 0.f;
  float dcs = cur - sh;
  g_xk[t] = fmaf(dcs, mk[d], sh);
  g_xr[t] = fmaf(dcs, mr[d], sh);
}

// ---------------- WKV scan, software-pipelined groups of 8 -------------------
#define WG 8
__device__ __forceinline__ void wkv_load(const float* kp, const float* vp,
                                         const float* rp, long off0,
                                         float* kb, float* vb, float* rb){
  #pragma unroll
  for(int j=0;j<WG;j++){
    long off = off0 + (long)j*DIM;
    kb[j] = __ldg(kp + off); vb[j] = __ldg(vp + off); rb[j] = __ldg(rp + off);
  }
}
__device__ __forceinline__ void wkv_step(float* kb, float* vb, float* rb,
                                         float* op, long off0,
                                         float w, float u,
                                         float& aa, float& bb, float& pp){
  #pragma unroll
  for(int j=0;j<WG;j++){
    float kt = kb[j], vt = vb[j];
    float ww = u + kt;
    float p  = fmaxf(pp, ww);
    float e1 = __expf(pp - p), e2 = __expf(ww - p);
    float o  = (e1*aa + e2*vt) / (e1*bb + e2);
    op[off0 + (long)j*DIM] = rb[j] * o;
    float ww2 = pp + w;
    float p2  = fmaxf(ww2, kt);
    e1 = __expf(ww2 - p2); e2 = __expf(kt - p2);
    aa = e1*aa + e2*vt; bb = e1*bb + e2; pp = p2;
  }
}
__global__ void wkv_k(const float* __restrict__ k, const float* __restrict__ v,
                      const float* __restrict__ r,
                      const float* __restrict__ dec, const float* __restrict__ fir,
                      float* __restrict__ out){
  int t = blockIdx.x*blockDim.x + threadIdx.x;   // 4096 threads (b,d)
  int d = t & (DIM-1); int b = t >> 9;
  float w = -__expf(dec[d]);
  float u = fir[d];
  float aa = 0.f, bb = 0.f, pp = -1e38f;
  long base = (long)b*USEQ*DIM + d;
  const float* kp = k + base;
  const float* vp = v + base;
  const float* rp = r + base;
  float* op = out + base;
  const int NG = USEQ/WG;   // 128 groups
  float k0b[WG], v0b[WG], r0b[WG];
  float k1b[WG], v1b[WG], r1b[WG];
  wkv_load(kp, vp, rp, 0, k0b, v0b, r0b);
  for(int g=0; g<NG; g+=2){
    long off1 = (long)(g+1)*WG*DIM;
    wkv_load(kp, vp, rp, off1, k1b, v1b, r1b);
    wkv_step(k0b, v0b, r0b, op, (long)g*WG*DIM, w, u, aa, bb, pp);
    if(g+2 < NG){
      long off2 = (long)(g+2)*WG*DIM;
      wkv_load(kp, vp, rp, off2, k0b, v0b, r0b);
    }
    wkv_step(k1b, v1b, r1b, op, off1, w, u, aa, bb, pp);
  }
}

// ---------------- olens tail --------------------------------------------------
__global__ void tail_k(const int* __restrict__ x_len, float* __restrict__ out, int out_size){
  int b = threadIdx.x;
  if(b < BATCH && out_size >= HTOK + BATCH){
    int l1 = (x_len[b] - 1)/2 + 1;
    int ol = (l1 - 1)/2 + 1;
    out[HTOK + b] = (float)ol;
  }
}

// ---------------- host side ---------------------------------------------------
template <typename T>
static float* symaddr(const T& s){ void* p = nullptr; cudaGetSymbolAddress(&p, s); return (float*)p; }

template<int ACT, int EPI>
static void gemm(int M, int N, int K, const float* A, const float* W,
                 const float* bias, float* C, const float* mul){
  dim3 grid(N/128, M/128);
  sgemm_k<ACT,EPI><<<grid, 256>>>(M, N, K, A, W, bias, C, mul);
}

extern "C" void kernel_launch(void* const* d_in, const int* in_sizes, int n_in,
                              void* d_out, int out_size){
  const float* x       = (const float*)d_in[0];
  const int*   x_len   = (const int*)  d_in[1];
  const float* conv1_w = (const float*)d_in[2];
  const float* conv1_b = (const float*)d_in[3];
  const float* conv2_w = (const float*)d_in[4];
  const float* conv2_b = (const float*)d_in[5];
  const float* conv3_w = (const float*)d_in[6];
  const float* conv3_b = (const float*)d_in[7];
  const float* embed_w = (const float*)d_in[8];
  const float* embed_b = (const float*)d_in[9];
  const float* eln_g   = (const float*)d_in[10];
  const float* eln_b   = (const float*)d_in[11];
  const float* lag     = (const float*)d_in[12];
  const float* lab     = (const float*)d_in[13];
  const float* dec     = (const float*)d_in[14];
  const float* fir     = (const float*)d_in[15];
  const float* amk     = (const float*)d_in[16];
  const float* amv     = (const float*)d_in[17];
  const float* amr     = (const float*)d_in[18];
  const float* awk     = (const float*)d_in[19];
  const float* awv     = (const float*)d_in[20];
  const float* awr     = (const float*)d_in[21];
  const float* awo     = (const float*)d_in[22];
  const float* lfg     = (const float*)d_in[23];
  const float* lfb     = (const float*)d_in[24];
  const float* fmk     = (const float*)d_in[25];
  const float* fmr     = (const float*)d_in[26];
  const float* fwk     = (const float*)d_in[27];
  const float* fwv     = (const float*)d_in[28];
  const float* fwr     = (const float*)d_in[29];
  const float* flg     = (const float*)d_in[30];
  const float* flb     = (const float*)d_in[31];
  float* out = (float*)d_out;

  float* p_col2 = symaddr(g_col2);
  float* p_c2   = symaddr(g_c2);
  float* p_col3 = symaddr(g_col3);
  float* p_c3   = symaddr(g_c3);
  float* p_yr   = symaddr(g_yr);
  float* p_t0   = symaddr(g_t0);
  float* p_h    = symaddr(g_h);
  float* p_xn   = symaddr(g_xn);
  float* p_xk   = symaddr(g_xk);
  float* p_xv   = symaddr(g_xv);
  float* p_xr   = symaddr(g_xr);
  float* p_k    = symaddr(g_k);
  float* p_v    = symaddr(g_v);
  float* p_r    = symaddr(g_r);
  float* p_rwkv = symaddr(g_rwkv);
  float* p_kk   = symaddr(g_kk);
  float* p_w2r  = symaddr(g_w2r);
  float* p_w3r  = symaddr(g_w3r);

  // conv frontend
  conv1_k<<<(BATCH*H1*W1*C1)/256, 256>>>(x, conv1_w, conv1_b);
  reorder_w2<<<(C2*C1*9 + 255)/256, 256>>>(conv2_w);
  reorder_w3<<<(C3*C2*9 + 255)/256, 256>>>(conv3_w);
  im2col2_k<<<(MCONV*(K2C/4))/256, 256>>>();
  gemm<1,0>(MCONV, C2, K2C, p_col2, p_w2r, conv2_b, p_c2, nullptr);
  im2col3_k<<<(MCONV*(K3C/4))/256, 256>>>();
  gemm<1,0>(MCONV, C3, K3C, p_col3, p_w3r, conv3_b, p_c3, nullptr);
  reshape_k<<<MT, 256>>>();
  gemm<0,0>(MT, DIM, KE, p_yr, embed_w, embed_b, p_t0, nullptr);
  ln_k<<<MT, 128>>>(p_t0, eln_g, eln_b, p_h);

  // RWKV blocks
  for(int i=0; i<NB_; i++){
    long w2 = (long)i*DIM*DIM;
    // time mixing
    ln_k<<<MT, 128>>>(p_h, lag + i*DIM, lab + i*DIM, p_xn);
    mix3_k<<<HTOK/256, 256>>>(p_xn, amk + i*DIM, amv + i*DIM, amr + i*DIM);
    gemm<0,0>(MT, DIM, DIM, p_xk, awk + w2, nullptr, p_k, nullptr);
    gemm<0,0>(MT, DIM, DIM, p_xv, awv + w2, nullptr, p_v, nullptr);
    gemm<2,0>(MT, DIM, DIM, p_xr, awr + w2, nullptr, p_r, nullptr);
    wkv_k<<<(BATCH*DIM)/256, 256>>>(p_k, p_v, p_r, dec + i*DIM, fir + i*DIM, p_rwkv);
    gemm<0,1>(MT, DIM, DIM, p_rwkv, awo + w2, nullptr, p_h, nullptr);
    // channel mixing
    ln_k<<<MT, 128>>>(p_h, lfg + i*DIM, lfb + i*DIM, p_xn);
    mix2_k<<<HTOK/256, 256>>>(p_xn, fmk + i*DIM, fmr + i*DIM);
    gemm<3,0>(MT, HID, DIM, p_xk, fwk + (long)i*DIM*HID, nullptr, p_kk, nullptr);
    gemm<2,0>(MT, DIM, DIM, p_xr, fwr + w2, nullptr, p_r, nullptr);
    gemm<0,2>(MT, DIM, HID, p_kk, fwv + (long)i*HID*DIM, nullptr, p_h, p_r);
  }

  ln_k<<<MT, 128>>>(p_h, flg, flb, out);
  tail_k<<<1, 32>>>(x_len, out, out_size);
}

// round 5
// speedup vs baseline: 2.3588x; 2.0171x over previous
#include <cuda_runtime.h>
#include <cuda_bf16.h>
#include <cstdint>

#define NB_   4
#define BATCH 8
#define LEN   4096
#define FREQ  80
#define DIM   512
#define HID   2048
#define USEQ  1024
#define C1    128
#define C2    256
#define C3    512
#define H1    2048
#define W1    40
#define H2    1024
#define W2    20
#define MCONV (BATCH*H2*W2)      /* 163840 */
#define K2C   (9*C1)             /* 1152 */
#define K3C   (9*C2)             /* 2304 */
#define KE    (C3*W2)            /* 10240 */
#define MT    (BATCH*USEQ)       /* 8192 */
#define HTOK  (MT*DIM)           /* 4194304 */

// ---------------- scratch (device globals; no allocations) ----------------
__device__ float g_conv1[BATCH*H1*W1*C1];   // (b,h,w,c) channel-last
__device__ float g_col2[MCONV*K2C];
__device__ float g_c2[MCONV*C2];            // (b,h,w,c)
__device__ float g_col3[MCONV*K3C];
__device__ float g_c3[MCONV*C3];            // (b,u,w,c)
__device__ float g_yr[MT*KE];
__device__ float g_t0[HTOK];
__device__ float g_h[HTOK];
__device__ float g_xn[HTOK];
__device__ float g_xk[HTOK];
__device__ float g_xv[HTOK];
__device__ float g_xr[HTOK];
__device__ float g_k[HTOK];
__device__ float g_v[HTOK];
__device__ float g_r[HTOK];
__device__ float g_rwkv[HTOK];
__device__ float g_kk[MT*HID];
// transposed weights, [N][K] K-major
__device__ float g_w2T[C2*K2C];
__device__ float g_w3T[C3*K3C];
__device__ float g_ewT[DIM*KE];
__device__ float g_awkT[NB_*DIM*DIM];
__device__ float g_awvT[NB_*DIM*DIM];
__device__ float g_awrT[NB_*DIM*DIM];
__device__ float g_awoT[NB_*DIM*DIM];
__device__ float g_fwkT[NB_*HID*DIM];
__device__ float g_fwvT[NB_*DIM*HID];
__device__ float g_fwrT[NB_*DIM*DIM];

// ================== warp-MMA helpers ==================
__device__ __forceinline__ uint32_t smem_to_u32(const void* p) {
  uint32_t a;
  asm("{ .reg .u64 t; cvta.to.shared.u64 t, %1; cvt.u32.u64 %0, t; }"
      : "=r"(a) : "l"(p));
  return a;
}
__device__ __forceinline__ void ldsm4(uint32_t* r, uint32_t addr){
  asm volatile("ldmatrix.sync.aligned.m8n8.x4.shared.b16 {%0,%1,%2,%3}, [%4];"
    : "=r"(r[0]),"=r"(r[1]),"=r"(r[2]),"=r"(r[3]) : "r"(addr));
}
__device__ __forceinline__ void mma_bf16(float* d, const uint32_t* a, const uint32_t* b){
  asm volatile("mma.sync.aligned.m16n8k16.row.col.f32.bf16.bf16.f32 "
    "{%0,%1,%2,%3}, {%4,%5,%6,%7}, {%8,%9}, {%0,%1,%2,%3};"
    : "+f"(d[0]),"+f"(d[1]),"+f"(d[2]),"+f"(d[3])
    : "r"(a[0]),"r"(a[1]),"r"(a[2]),"r"(a[3]), "r"(b[0]),"r"(b[1]));
}
// split 4 floats into bf16 hi pairs + bf16 lo-residual pairs
__device__ __forceinline__ void split4(float4 v, uint2& hi, uint2& lo){
  __nv_bfloat162 h01 = __floats2bfloat162_rn(v.x, v.y);
  __nv_bfloat162 h23 = __floats2bfloat162_rn(v.z, v.w);
  float rx = v.x - __bfloat162float(h01.x);
  float ry = v.y - __bfloat162float(h01.y);
  float rz = v.z - __bfloat162float(h23.x);
  float rw = v.w - __bfloat162float(h23.y);
  __nv_bfloat162 l01 = __floats2bfloat162_rn(rx, ry);
  __nv_bfloat162 l23 = __floats2bfloat162_rn(rz, rw);
  hi.x = *(uint32_t*)&h01; hi.y = *(uint32_t*)&h23;
  lo.x = *(uint32_t*)&l01; lo.y = *(uint32_t*)&l23;
}

// ====== bf16x3 MMA GEMM: CTA tile 128x128, Kchunk=32, 8 warps (32x64 each) ===
// C[M,N] = epi(act(A[M,K] @ Wt[N,K]^T + bias))
// ACT: 0 none, 1 relu, 2 sigmoid, 3 relu^2 ; EPI: 0 store, 1 C+=acc, 2 C+=mul*acc
#define PITCH 40                /* bf16 per smem row (80B, conflict-free ldsm) */
#define AHI_O 0
#define ALO_O 10240
#define BHI_O 20480
#define BLO_O 30720
#define STG_B 40960
#define MSMEM (2*STG_B)

template<int ACT, int EPI>
__global__ void __launch_bounds__(256, 1) mgemm_k(int M, int N, int K,
    const float* __restrict__ A, const float* __restrict__ Wt,
    const float* __restrict__ bias, float* __restrict__ C,
    const float* __restrict__ mul){
  extern __shared__ char smarr[];
  uint32_t smb = smem_to_u32(smarr);
  int tid = threadIdx.x, lane = tid & 31, wid = tid >> 5;
  int wm = wid >> 1, wn = wid & 1;          // warp grid 4(m) x 2(n)
  long m0 = (long)blockIdx.y * 128;
  int  n0 = blockIdx.x * 128;

  int row = tid >> 1, cb = (tid & 1) * 16;  // global->smem loader mapping
  const float* Ap = A  + (m0 + row)*(long)K + cb;
  const float* Bp = Wt + ((long)n0 + row)*K + cb;
  uint32_t stoff = (uint32_t)(row*PITCH + cb) * 2;

  // ldmatrix per-lane byte offsets within hi arrays
  uint32_t aoff = (((uint32_t)wm*32 + ((lane>>3)&1)*8 + (lane&7))*PITCH + ((lane>>4)&1)*8) * 2;
  uint32_t boff = (((uint32_t)wn*64 + ((lane>>4)&1)*8 + (lane&7))*PITCH + ((lane>>3)&1)*8) * 2;

  float acc[2][8][4];
  #pragma unroll
  for(int i=0;i<2;i++)
    #pragma unroll
    for(int j=0;j<8;j++)
      #pragma unroll
      for(int q=0;q<4;q++) acc[i][j][q] = 0.f;

  int nc = K >> 5;
  float4 av[4], bv[4];
  #pragma unroll
  for(int q=0;q<4;q++){ av[q] = *(const float4*)(Ap + q*4); bv[q] = *(const float4*)(Bp + q*4); }
  {
    char* sp = smarr;
    #pragma unroll
    for(int q=0;q<4;q++){
      uint2 h, l;
      split4(av[q], h, l);
      *(uint2*)(sp + AHI_O + stoff + q*8) = h;
      *(uint2*)(sp + ALO_O + stoff + q*8) = l;
      split4(bv[q], h, l);
      *(uint2*)(sp + BHI_O + stoff + q*8) = h;
      *(uint2*)(sp + BLO_O + stoff + q*8) = l;
    }
  }
  __syncthreads();

  for(int c = 0; c < nc; c++){
    if(c + 1 < nc){
      const float* ap = Ap + (c+1)*32;
      const float* bp = Bp + (c+1)*32;
      #pragma unroll
      for(int q=0;q<4;q++){ av[q] = *(const float4*)(ap + q*4); bv[q] = *(const float4*)(bp + q*4); }
    }
    uint32_t stg = smb + (c & 1)*STG_B;
    #pragma unroll
    for(int ks = 0; ks < 2; ks++){
      uint32_t ahk[2][4], alk[2][4], bhk[4][4], blk[4][4];
      #pragma unroll
      for(int mt = 0; mt < 2; mt++){
        uint32_t ad = stg + AHI_O + aoff + mt*(16*PITCH*2) + ks*32;
        ldsm4(ahk[mt], ad);
        ldsm4(alk[mt], ad + (ALO_O - AHI_O));
      }
      #pragma unroll
      for(int ng = 0; ng < 4; ng++){
        uint32_t bd = stg + BHI_O + boff + ng*(16*PITCH*2) + ks*32;
        ldsm4(bhk[ng], bd);
        ldsm4(blk[ng], bd + (BLO_O - BHI_O));
      }
      #pragma unroll
      for(int mt = 0; mt < 2; mt++)
        #pragma unroll
        for(int nt = 0; nt < 8; nt++)
          mma_bf16(acc[mt][nt], ahk[mt], &bhk[nt>>1][(nt&1)*2]);
      #pragma unroll
      for(int mt = 0; mt < 2; mt++)
        #pragma unroll
        for(int nt = 0; nt < 8; nt++)
          mma_bf16(acc[mt][nt], ahk[mt], &blk[nt>>1][(nt&1)*2]);
      #pragma unroll
      for(int mt = 0; mt < 2; mt++)
        #pragma unroll
        for(int nt = 0; nt < 8; nt++)
          mma_bf16(acc[mt][nt], alk[mt], &bhk[nt>>1][(nt&1)*2]);
    }
    if(c + 1 < nc){
      char* sp = smarr + ((c+1) & 1)*STG_B;
      #pragma unroll
      for(int q=0;q<4;q++){
        uint2 h, l;
        split4(av[q], h, l);
        *(uint2*)(sp + AHI_O + stoff + q*8) = h;
        *(uint2*)(sp + ALO_O + stoff + q*8) = l;
        split4(bv[q], h, l);
        *(uint2*)(sp + BHI_O + stoff + q*8) = h;
        *(uint2*)(sp + BLO_O + stoff + q*8) = l;
      }
    }
    __syncthreads();
  }

  // ---- epilogue: c0,c1 at (m=lane/4, n=(lane%3..)*2), c2,c3 at m+8 ----
  int mrow = lane >> 2;
  int ncol = (lane & 3) * 2;
  #pragma unroll
  for(int mt = 0; mt < 2; mt++){
    #pragma unroll
    for(int nt = 0; nt < 8; nt++){
      #pragma unroll
      for(int hf = 0; hf < 2; hf++){
        long gm = m0 + wm*32 + mt*16 + mrow + hf*8;
        int  gn = n0 + wn*64 + nt*8 + ncol;
        float v0 = acc[mt][nt][hf*2+0];
        float v1 = acc[mt][nt][hf*2+1];
        if(bias){ v0 += bias[gn]; v1 += bias[gn+1]; }
        if(ACT == 1){ v0 = fmaxf(v0,0.f); v1 = fmaxf(v1,0.f); }
        else if(ACT == 2){ v0 = 1.f/(1.f+__expf(-v0)); v1 = 1.f/(1.f+__expf(-v1)); }
        else if(ACT == 3){ v0 = fmaxf(v0,0.f); v0 *= v0; v1 = fmaxf(v1,0.f); v1 *= v1; }
        float* cp = C + gm*N + gn;
        if(EPI == 1){
          v0 += cp[0]; v1 += cp[1];
        } else if(EPI == 2){
          const float* mp = mul + gm*N + gn;
          v0 = cp[0] + mp[0]*v0; v1 = cp[1] + mp[1]*v1;
        }
        *(float2*)cp = make_float2(v0, v1);
      }
    }
  }
}

// ---------------- conv1: direct, (B,1,4096,80) -> (B,2048,40,128) ----------
__global__ void conv1_k(const float* __restrict__ x, const float* __restrict__ w,
                        const float* __restrict__ bias){
  int t = blockIdx.x*256 + threadIdx.x;
  int co = t & 127;
  int rest = t >> 7;
  int wo = rest % W1; rest /= W1;
  int ho = rest % H1; int b = rest / H1;
  float acc = bias[co];
  int hi0 = 2*ho - 1, wi0 = 2*wo - 1;
  #pragma unroll
  for(int kh=0; kh<3; kh++){
    int hi = hi0 + kh;
    if(hi < 0 || hi >= LEN) continue;
    #pragma unroll
    for(int kw=0; kw<3; kw++){
      int wi = wi0 + kw;
      if(wi < 0 || wi >= FREQ) continue;
      acc = fmaf(x[(hi + (long)b*LEN)*FREQ + wi], w[co*9 + kh*3 + kw], acc);
    }
  }
  g_conv1[t] = fmaxf(acc, 0.f);
}

// ---------------- conv weight reorders: OIHW -> [co][(kh*3+kw)*CI+ci] -------
__global__ void reorder_w2(const float* __restrict__ w){
  int t = blockIdx.x*256 + threadIdx.x;
  if(t >= C2*K2C) return;
  int co = t / K2C; int idx = t % K2C;
  int r = idx / C1; int ci = idx % C1;
  g_w2T[t] = w[co*(C1*9) + ci*9 + r];
}
__global__ void reorder_w3(const float* __restrict__ w){
  int t = blockIdx.x*256 + threadIdx.x;
  if(t >= C3*K3C) return;
  int co = t / K3C; int idx = t % K3C;
  int r = idx / C2; int ci = idx % C2;
  g_w3T[t] = w[co*(C2*9) + ci*9 + r];
}

// ---------------- generic transpose: in[R][C] -> out[C][R] -------------------
__global__ void transpose_k(const float* __restrict__ in, float* __restrict__ out,
                            int R, int C){
  __shared__ float tile[32][33];
  int c0 = blockIdx.x*32, r0 = blockIdx.y*32;
  int x = c0 + threadIdx.x;
  for(int dy = threadIdx.y; dy < 32; dy += 8){
    int r = r0 + dy;
    tile[dy][threadIdx.x] = (r < R && x < C) ? in[(long)r*C + x] : 0.f;
  }
  __syncthreads();
  int xo = r0 + threadIdx.x;
  for(int dy = threadIdx.y; dy < 32; dy += 8){
    int co = c0 + dy;
    if(co < C && xo < R) out[(long)co*R + xo] = tile[threadIdx.x][dy];
  }
}

// ---------------- im2col (float4 over channel dim) --------------------------
__global__ void im2col2_k(){
  int t = blockIdx.x*256 + threadIdx.x;
  int k4 = t % (K2C/4); int m = t / (K2C/4);
  int k = k4*4;
  int r = k >> 7; int ci = k & 127;
  int kh = r / 3, kw = r % 3;
  int wo = m % W2; int rest = m / W2;
  int ho = rest % H2; int b = rest / H2;
  int hi = 2*ho + kh - 1, wi = 2*wo + kw - 1;
  float4 v = make_float4(0.f,0.f,0.f,0.f);
  if(hi >= 0 && hi < H1 && wi >= 0 && wi < W1)
    v = *(const float4*)&g_conv1[((b*H1 + hi)*W1 + wi)*C1 + ci];
  *(float4*)&g_col2[(long)m*K2C + k] = v;
}
__global__ void im2col3_k(){
  int t = blockIdx.x*256 + threadIdx.x;
  int k4 = t % (K3C/4); int m = t / (K3C/4);
  int k = k4*4;
  int r = k >> 8; int ci = k & 255;
  int kh = r / 3, kw = r % 3;
  int wo = m % W2; int rest = m / W2;
  int ho = rest % H2; int b = rest / H2;
  int hi = ho + kh - 1, wi = wo + kw - 1;
  float4 v = make_float4(0.f,0.f,0.f,0.f);
  if(hi >= 0 && hi < H2 && wi >= 0 && wi < W2)
    v = *(const float4*)&g_c2[((b*H2 + hi)*W2 + wi)*C2 + ci];
  *(float4*)&g_col3[(long)m*K3C + k] = v;
}

// ---------------- reshape (b,u,w,c) -> (b,u, c*20+w) -------------------------
__global__ void reshape_k(){
  __shared__ float sm[KE];
  int m = blockIdx.x;
  const float* src = g_c3 + (long)m*KE;
  for(int i=threadIdx.x; i<KE; i+=256){
    int w = i / 512, c = i & 511;
    sm[c*W2 + w] = src[i];
  }
  __syncthreads();
  float* dst = g_yr + (long)m*KE;
  for(int i=threadIdx.x; i<KE; i+=256) dst[i] = sm[i];
}

// ---------------- LayerNorm over D=512, 128 threads per token ----------------
__global__ void ln_k(const float* __restrict__ x, const float* __restrict__ gw,
                     const float* __restrict__ gb, float* __restrict__ o){
  int m = blockIdx.x;
  int tid = threadIdx.x;
  const float* xr = x + (long)m*DIM;
  float v[4]; float s = 0.f, sq = 0.f;
  #pragma unroll
  for(int j=0;j<4;j++){ float t = xr[tid + j*128]; v[j] = t; s += t; sq += t*t; }
  #pragma unroll
  for(int off=16; off; off>>=1){
    s  += __shfl_xor_sync(0xffffffffu, s,  off);
    sq += __shfl_xor_sync(0xffffffffu, sq, off);
  }
  __shared__ float ss[4], sqs[4];
  if((tid & 31) == 0){ ss[tid>>5] = s; sqs[tid>>5] = sq; }
  __syncthreads();
  s  = (ss[0]+ss[1]) + (ss[2]+ss[3]);
  sq = (sqs[0]+sqs[1]) + (sqs[2]+sqs[3]);
  float mean = s * (1.f/DIM);
  float var  = sq * (1.f/DIM) - mean*mean;
  float rstd = rsqrtf(var + 1e-5f);
  float* orow = o + (long)m*DIM;
  #pragma unroll
  for(int j=0;j<4;j++){
    int d = tid + j*128;
    orow[d] = (v[j] - mean)*rstd*gw[d] + gb[d];
  }
}

// ---------------- time-shift mixes -------------------------------------------
__global__ void mix3_k(const float* __restrict__ xn, const float* __restrict__ mk,
                       const float* __restrict__ mv, const float* __restrict__ mr){
  int t = blockIdx.x*256 + threadIdx.x;
  int d = t & (DIM-1);
  int tok = (t >> 9) & (USEQ-1);
  float cur = xn[t];
  float sh = tok ? xn[t - DIM] : 0.f;
  float dcs = cur - sh;
  g_xk[t] = fmaf(dcs, mk[d], sh);
  g_xv[t] = fmaf(dcs, mv[d], sh);
  g_xr[t] = fmaf(dcs, mr[d], sh);
}
__global__ void mix2_k(const float* __restrict__ xn, const float* __restrict__ mk,
                       const float* __restrict__ mr){
  int t = blockIdx.x*256 + threadIdx.x;
  int d = t & (DIM-1);
  int tok = (t >> 9) & (USEQ-1);
  float cur = xn[t];
  float sh = tok ? xn[t - DIM] : 0.f;
  float dcs = cur - sh;
  g_xk[t] = fmaf(dcs, mk[d], sh);
  g_xr[t] = fmaf(dcs, mr[d], sh);
}

// ---------------- WKV scan, software-pipelined groups of 8 -------------------
#define WG 8
__device__ __forceinline__ void wkv_load(const float* kp, const float* vp,
                                         const float* rp, long off0,
                                         float* kb, float* vb, float* rb){
  #pragma unroll
  for(int j=0;j<WG;j++){
    long off = off0 + (long)j*DIM;
    kb[j] = __ldg(kp + off); vb[j] = __ldg(vp + off); rb[j] = __ldg(rp + off);
  }
}
__device__ __forceinline__ void wkv_step(float* kb, float* vb, float* rb,
                                         float* op, long off0,
                                         float w, float u,
                                         float& aa, float& bb, float& pp){
  #pragma unroll
  for(int j=0;j<WG;j++){
    float kt = kb[j], vt = vb[j];
    float ww = u + kt;
    float p  = fmaxf(pp, ww);
    float e1 = __expf(pp - p), e2 = __expf(ww - p);
    float o  = (e1*aa + e2*vt) / (e1*bb + e2);
    op[off0 + (long)j*DIM] = rb[j] * o;
    float ww2 = pp + w;
    float p2  = fmaxf(ww2, kt);
    e1 = __expf(ww2 - p2); e2 = __expf(kt - p2);
    aa = e1*aa + e2*vt; bb = e1*bb + e2; pp = p2;
  }
}
__global__ void wkv_k(const float* __restrict__ k, const float* __restrict__ v,
                      const float* __restrict__ r,
                      const float* __restrict__ dec, const float* __restrict__ fir,
                      float* __restrict__ out){
  int t = blockIdx.x*blockDim.x + threadIdx.x;
  int d = t & (DIM-1); int b = t >> 9;
  float w = -__expf(dec[d]);
  float u = fir[d];
  float aa = 0.f, bb = 0.f, pp = -1e38f;
  long base = (long)b*USEQ*DIM + d;
  const float* kp = k + base;
  const float* vp = v + base;
  const float* rp = r + base;
  float* op = out + base;
  const int NG = USEQ/WG;
  float k0b[WG], v0b[WG], r0b[WG];
  float k1b[WG], v1b[WG], r1b[WG];
  wkv_load(kp, vp, rp, 0, k0b, v0b, r0b);
  for(int g=0; g<NG; g+=2){
    long off1 = (long)(g+1)*WG*DIM;
    wkv_load(kp, vp, rp, off1, k1b, v1b, r1b);
    wkv_step(k0b, v0b, r0b, op, (long)g*WG*DIM, w, u, aa, bb, pp);
    if(g+2 < NG){
      long off2 = (long)(g+2)*WG*DIM;
      wkv_load(kp, vp, rp, off2, k0b, v0b, r0b);
    }
    wkv_step(k1b, v1b, r1b, op, off1, w, u, aa, bb, pp);
  }
}

// ---------------- olens tail --------------------------------------------------
__global__ void tail_k(const int* __restrict__ x_len, float* __restrict__ out, int out_size){
  int b = threadIdx.x;
  if(b < BATCH && out_size >= HTOK + BATCH){
    int l1 = (x_len[b] - 1)/2 + 1;
    int ol = (l1 - 1)/2 + 1;
    out[HTOK + b] = (float)ol;
  }
}

// ---------------- host side ---------------------------------------------------
template <typename T>
static float* symaddr(const T& s){ void* p = nullptr; cudaGetSymbolAddress(&p, s); return (float*)p; }

template<int ACT, int EPI>
static void gemm(int M, int N, int K, const float* A, const float* Wt,
                 const float* bias, float* C, const float* mul){
  cudaFuncSetAttribute(mgemm_k<ACT,EPI>, cudaFuncAttributeMaxDynamicSharedMemorySize, MSMEM);
  dim3 grid(N/128, M/128);
  mgemm_k<ACT,EPI><<<grid, 256, MSMEM>>>(M, N, K, A, Wt, bias, C, mul);
}

extern "C" void kernel_launch(void* const* d_in, const int* in_sizes, int n_in,
                              void* d_out, int out_size){
  const float* x       = (const float*)d_in[0];
  const int*   x_len   = (const int*)  d_in[1];
  const float* conv1_w = (const float*)d_in[2];
  const float* conv1_b = (const float*)d_in[3];
  const float* conv2_w = (const float*)d_in[4];
  const float* conv2_b = (const float*)d_in[5];
  const float* conv3_w = (const float*)d_in[6];
  const float* conv3_b = (const float*)d_in[7];
  const float* embed_w = (const float*)d_in[8];
  const float* embed_b = (const float*)d_in[9];
  const float* eln_g   = (const float*)d_in[10];
  const float* eln_b   = (const float*)d_in[11];
  const float* lag     = (const float*)d_in[12];
  const float* lab     = (const float*)d_in[13];
  const float* dec     = (const float*)d_in[14];
  const float* fir     = (const float*)d_in[15];
  const float* amk     = (const float*)d_in[16];
  const float* amv     = (const float*)d_in[17];
  const float* amr     = (const float*)d_in[18];
  const float* awk     = (const float*)d_in[19];
  const float* awv     = (const float*)d_in[20];
  const float* awr     = (const float*)d_in[21];
  const float* awo     = (const float*)d_in[22];
  const float* lfg     = (const float*)d_in[23];
  const float* lfb     = (const float*)d_in[24];
  const float* fmk     = (const float*)d_in[25];
  const float* fmr     = (const float*)d_in[26];
  const float* fwk     = (const float*)d_in[27];
  const float* fwv     = (const float*)d_in[28];
  const float* fwr     = (const float*)d_in[29];
  const float* flg     = (const float*)d_in[30];
  const float* flb     = (const float*)d_in[31];
  float* out = (float*)d_out;

  float* p_col2 = symaddr(g_col2);
  float* p_c2   = symaddr(g_c2);
  float* p_col3 = symaddr(g_col3);
  float* p_yr   = symaddr(g_yr);
  float* p_t0   = symaddr(g_t0);
  float* p_h    = symaddr(g_h);
  float* p_xn   = symaddr(g_xn);
  float* p_xk   = symaddr(g_xk);
  float* p_xv   = symaddr(g_xv);
  float* p_xr   = symaddr(g_xr);
  float* p_k    = symaddr(g_k);
  float* p_v    = symaddr(g_v);
  float* p_r    = symaddr(g_r);
  float* p_rwkv = symaddr(g_rwkv);
  float* p_kk   = symaddr(g_kk);
  float* p_c3   = symaddr(g_c3);
  float* p_w2T  = symaddr(g_w2T);
  float* p_w3T  = symaddr(g_w3T);
  float* p_ewT  = symaddr(g_ewT);
  float* p_awkT = symaddr(g_awkT);
  float* p_awvT = symaddr(g_awvT);
  float* p_awrT = symaddr(g_awrT);
  float* p_awoT = symaddr(g_awoT);
  float* p_fwkT = symaddr(g_fwkT);
  float* p_fwvT = symaddr(g_fwvT);
  float* p_fwrT = symaddr(g_fwrT);

  // ---- weight prep ----
  reorder_w2<<<(C2*K2C + 255)/256, 256>>>(conv2_w);
  reorder_w3<<<(C3*K3C + 255)/256, 256>>>(conv3_w);
  transpose_k<<<dim3(DIM/32, KE/32), dim3(32,8)>>>(embed_w, p_ewT, KE, DIM);
  for(int i = 0; i < NB_; i++){
    long o2 = (long)i*DIM*DIM;
    long oh = (long)i*DIM*HID;
    transpose_k<<<dim3(16,16), dim3(32,8)>>>(awk + o2, p_awkT + o2, DIM, DIM);
    transpose_k<<<dim3(16,16), dim3(32,8)>>>(awv + o2, p_awvT + o2, DIM, DIM);
    transpose_k<<<dim3(16,16), dim3(32,8)>>>(awr + o2, p_awrT + o2, DIM, DIM);
    transpose_k<<<dim3(16,16), dim3(32,8)>>>(awo + o2, p_awoT + o2, DIM, DIM);
    transpose_k<<<dim3(HID/32, DIM/32), dim3(32,8)>>>(fwk + oh, p_fwkT + oh, DIM, HID);
    transpose_k<<<dim3(DIM/32, HID/32), dim3(32,8)>>>(fwv + oh, p_fwvT + oh, HID, DIM);
    transpose_k<<<dim3(16,16), dim3(32,8)>>>(fwr + o2, p_fwrT + o2, DIM, DIM);
  }

  // ---- conv frontend ----
  conv1_k<<<(BATCH*H1*W1*C1)/256, 256>>>(x, conv1_w, conv1_b);
  im2col2_k<<<(MCONV*(K2C/4))/256, 256>>>();
  gemm<1,0>(MCONV, C2, K2C, p_col2, p_w2T, conv2_b, p_c2, nullptr);
  im2col3_k<<<(MCONV*(K3C/4))/256, 256>>>();
  gemm<1,0>(MCONV, C3, K3C, p_col3, p_w3T, conv3_b, p_c3, nullptr);
  reshape_k<<<MT, 256>>>();
  gemm<0,0>(MT, DIM, KE, p_yr, p_ewT, embed_b, p_t0, nullptr);
  ln_k<<<MT, 128>>>(p_t0, eln_g, eln_b, p_h);

  // ---- RWKV blocks ----
  for(int i = 0; i < NB_; i++){
    long w2 = (long)i*DIM*DIM;
    long wh = (long)i*DIM*HID;
    // time mixing
    ln_k<<<MT, 128>>>(p_h, lag + i*DIM, lab + i*DIM, p_xn);
    mix3_k<<<HTOK/256, 256>>>(p_xn, amk + i*DIM, amv + i*DIM, amr + i*DIM);
    gemm<0,0>(MT, DIM, DIM, p_xk, p_awkT + w2, nullptr, p_k, nullptr);
    gemm<0,0>(MT, DIM, DIM, p_xv, p_awvT + w2, nullptr, p_v, nullptr);
    gemm<2,0>(MT, DIM, DIM, p_xr, p_awrT + w2, nullptr, p_r, nullptr);
    wkv_k<<<(BATCH*DIM)/256, 256>>>(p_k, p_v, p_r, dec + i*DIM, fir + i*DIM, p_rwkv);
    gemm<0,1>(MT, DIM, DIM, p_rwkv, p_awoT + w2, nullptr, p_h, nullptr);
    // channel mixing
    ln_k<<<MT, 128>>>(p_h, lfg + i*DIM, lfb + i*DIM, p_xn);
    mix2_k<<<HTOK/256, 256>>>(p_xn, fmk + i*DIM, fmr + i*DIM);
    gemm<3,0>(MT, HID, DIM, p_xk, p_fwkT + wh, nullptr, p_kk, nullptr);
    gemm<2,0>(MT, DIM, DIM, p_xr, p_fwrT + w2, nullptr, p_r, nullptr);
    gemm<0,2>(MT, DIM, HID, p_kk, p_fwvT + wh, nullptr, p_h, p_r);
  }

  ln_k<<<MT, 128>>>(p_h, flg, flb, out);
  tail_k<<<1, 32>>>(x_len, out, out_size);
}

// round 6
// speedup vs baseline: 2.3634x; 1.0019x over previous
#include <cuda_runtime.h>
#include <cuda_bf16.h>
#include <cstdint>

typedef __nv_bfloat16 bf;

#define NB_   4
#define BATCH 8
#define LEN   4096
#define FREQ  80
#define DIM   512
#define HID   2048
#define USEQ  1024
#define C1    128
#define C2    256
#define C3    512
#define H1    2048
#define W1    40
#define H2    1024
#define W2    20
#define MCONV (BATCH*H2*W2)      /* 163840 */
#define K2C   (9*C1)             /* 1152 */
#define K3C   (9*C2)             /* 2304 */
#define KE    (C3*W2)            /* 10240 */
#define MT    (BATCH*USEQ)       /* 8192 */
#define HTOK  (MT*DIM)           /* 4194304 */

// ---------------- scratch (device globals; no allocations) ----------------
__device__ float g_conv1[BATCH*H1*W1*C1];   // (b,h,w,c) channel-last fp32
__device__ bf g_col2h[MCONV*K2C],  g_col2l[MCONV*K2C];
__device__ bf g_c2h[MCONV*C2],     g_c2l[MCONV*C2];
__device__ bf g_col3h[MCONV*K3C],  g_col3l[MCONV*K3C];
__device__ bf g_c3h[MCONV*C3],     g_c3l[MCONV*C3];
__device__ bf g_yrh[MT*KE],        g_yrl[MT*KE];
__device__ float g_t0[HTOK];
__device__ float g_h[HTOK];
__device__ float g_xn[HTOK];
__device__ bf g_xkh[HTOK], g_xkl[HTOK];
__device__ bf g_xvh[HTOK], g_xvl[HTOK];
__device__ bf g_xrh[HTOK], g_xrl[HTOK];
__device__ float g_k[HTOK];
__device__ float g_v[HTOK];
__device__ float g_r[HTOK];
__device__ bf g_rwh[HTOK], g_rwl[HTOK];
__device__ bf g_kkh[MT*HID], g_kkl[MT*HID];
// transposed+split weights, [N][K] K-major bf16 hi/lo
__device__ bf g_w2Th[C2*K2C],  g_w2Tl[C2*K2C];
__device__ bf g_w3Th[C3*K3C],  g_w3Tl[C3*K3C];
__device__ bf g_ewTh[DIM*KE],  g_ewTl[DIM*KE];
__device__ bf g_awkTh[NB_*DIM*DIM], g_awkTl[NB_*DIM*DIM];
__device__ bf g_awvTh[NB_*DIM*DIM], g_awvTl[NB_*DIM*DIM];
__device__ bf g_awrTh[NB_*DIM*DIM], g_awrTl[NB_*DIM*DIM];
__device__ bf g_awoTh[NB_*DIM*DIM], g_awoTl[NB_*DIM*DIM];
__device__ bf g_fwkTh[NB_*HID*DIM], g_fwkTl[NB_*HID*DIM];
__device__ bf g_fwvTh[NB_*DIM*HID], g_fwvTl[NB_*DIM*HID];
__device__ bf g_fwrTh[NB_*DIM*DIM], g_fwrTl[NB_*DIM*DIM];

// ================== helpers ==================
__device__ __forceinline__ uint32_t smem_to_u32(const void* p) {
  uint32_t a;
  asm("{ .reg .u64 t; cvta.to.shared.u64 t, %1; cvt.u32.u64 %0, t; }"
      : "=r"(a) : "l"(p));
  return a;
}
__device__ __forceinline__ void ldsm4(uint32_t* r, uint32_t addr){
  asm volatile("ldmatrix.sync.aligned.m8n8.x4.shared.b16 {%0,%1,%2,%3}, [%4];"
    : "=r"(r[0]),"=r"(r[1]),"=r"(r[2]),"=r"(r[3]) : "r"(addr));
}
__device__ __forceinline__ void mma_bf16(float* d, const uint32_t* a, const uint32_t* b){
  asm volatile("mma.sync.aligned.m16n8k16.row.col.f32.bf16.bf16.f32 "
    "{%0,%1,%2,%3}, {%4,%5,%6,%7}, {%8,%9}, {%0,%1,%2,%3};"
    : "+f"(d[0]),"+f"(d[1]),"+f"(d[2]),"+f"(d[3])
    : "r"(a[0]),"r"(a[1]),"r"(a[2]),"r"(a[3]), "r"(b[0]),"r"(b[1]));
}
__device__ __forceinline__ void cp16(uint32_t s, const void* g){
  asm volatile("cp.async.cg.shared.global [%0], [%1], 16;" :: "r"(s), "l"(g));
}
#define CP_COMMIT() asm volatile("cp.async.commit_group;" ::: "memory")
#define CP_WAIT1()  asm volatile("cp.async.wait_group 1;" ::: "memory")

__device__ __forceinline__ void split2(float v0, float v1, uint32_t& h, uint32_t& l){
  __nv_bfloat162 hh = __floats2bfloat162_rn(v0, v1);
  float r0 = v0 - __bfloat162float(hh.x);
  float r1 = v1 - __bfloat162float(hh.y);
  __nv_bfloat162 ll = __floats2bfloat162_rn(r0, r1);
  h = *(uint32_t*)&hh; l = *(uint32_t*)&ll;
}
__device__ __forceinline__ void split4(float4 v, uint2& hi, uint2& lo){
  split2(v.x, v.y, hi.x, lo.x);
  split2(v.z, v.w, hi.y, lo.y);
}

// ====== bf16x3 MMA GEMM: CTA 128x128, Kchunk=32, 8 warps, cp.async 3-stage ===
// C = epi(act(A @ Wt^T + bias));  A,Wt pre-split bf16 hi/lo, K-major
// ACT: 0 none,1 relu,2 sigmoid,3 relu^2 ; EPI: 0 store,1 +=,2 C+mul*acc
// OUT: 0 fp32 C ; 1 bf16 hi/lo (Ch,Cl)
#define PITCH 40                /* bf16 per smem row (80B) */
#define AHI_O 0
#define ALO_O 10240
#define BHI_O 20480
#define BLO_O 30720
#define STG_B 40960
#define MSMEM (3*STG_B)

template<int ACT, int EPI, int OUT>
__global__ void __launch_bounds__(256, 1) mgemm_k(int M, int N, int K,
    const bf* __restrict__ Ah, const bf* __restrict__ Al,
    const bf* __restrict__ Bh, const bf* __restrict__ Bl,
    const float* __restrict__ bias, float* __restrict__ C,
    bf* __restrict__ Ch, bf* __restrict__ Cl, const float* __restrict__ mul){
  extern __shared__ char smarr[];
  uint32_t smb = smem_to_u32(smarr);
  int tid = threadIdx.x, lane = tid & 31, wid = tid >> 5;
  int wm = wid >> 1, wn = wid & 1;          // warp grid 4(m) x 2(n)
  long m0 = (long)blockIdx.y * 128;
  int  n0 = blockIdx.x * 128;

  int lrow = tid >> 1;                      // loader row 0..127
  long lga = (m0 + lrow)*(long)K + (tid & 1)*16;
  long lgb = ((long)n0 + lrow)*K + (tid & 1)*16;
  uint32_t lso = (uint32_t)lrow*80 + (tid & 1)*32;

  // ldmatrix per-lane byte offsets
  uint32_t aoff = (((uint32_t)wm*32 + ((lane>>3)&1)*8 + (lane&7))*PITCH + ((lane>>4)&1)*8) * 2;
  uint32_t boff = (((uint32_t)wn*64 + ((lane>>4)&1)*8 + (lane&7))*PITCH + ((lane>>3)&1)*8) * 2;

  float acc[2][8][4];
  #pragma unroll
  for(int i=0;i<2;i++)
    #pragma unroll
    for(int j=0;j<8;j++)
      #pragma unroll
      for(int q=0;q<4;q++) acc[i][j][q] = 0.f;

  int nc = K >> 5;

  #define LOAD_CHUNK(c, sidx) do { \
    uint32_t stg_ = smb + (sidx)*STG_B; \
    long go_ = (long)(c)*32; \
    cp16(stg_ + AHI_O + lso,      Ah + lga + go_); \
    cp16(stg_ + AHI_O + lso + 16, Ah + lga + go_ + 8); \
    cp16(stg_ + ALO_O + lso,      Al + lga + go_); \
    cp16(stg_ + ALO_O + lso + 16, Al + lga + go_ + 8); \
    cp16(stg_ + BHI_O + lso,      Bh + lgb + go_); \
    cp16(stg_ + BHI_O + lso + 16, Bh + lgb + go_ + 8); \
    cp16(stg_ + BLO_O + lso,      Bl + lgb + go_); \
    cp16(stg_ + BLO_O + lso + 16, Bl + lgb + go_ + 8); \
  } while(0)

  LOAD_CHUNK(0, 0); CP_COMMIT();
  LOAD_CHUNK(1, 1); CP_COMMIT();

  for(int c = 0; c < nc; c++){
    CP_WAIT1();
    __syncthreads();
    if(c + 2 < nc){ LOAD_CHUNK(c + 2, (c + 2) % 3); }
    CP_COMMIT();
    uint32_t stg = smb + (c % 3)*STG_B;
    #pragma unroll
    for(int ks = 0; ks < 2; ks++){
      uint32_t ahk[2][4], alk[2][4], bhk[4][4], blk[4][4];
      #pragma unroll
      for(int mt = 0; mt < 2; mt++){
        uint32_t ad = stg + AHI_O + aoff + mt*(16*PITCH*2) + ks*32;
        ldsm4(ahk[mt], ad);
        ldsm4(alk[mt], ad + (ALO_O - AHI_O));
      }
      #pragma unroll
      for(int ng = 0; ng < 4; ng++){
        uint32_t bd = stg + BHI_O + boff + ng*(16*PITCH*2) + ks*32;
        ldsm4(bhk[ng], bd);
        ldsm4(blk[ng], bd + (BLO_O - BHI_O));
      }
      #pragma unroll
      for(int mt = 0; mt < 2; mt++)
        #pragma unroll
        for(int nt = 0; nt < 8; nt++)
          mma_bf16(acc[mt][nt], ahk[mt], &bhk[nt>>1][(nt&1)*2]);
      #pragma unroll
      for(int mt = 0; mt < 2; mt++)
        #pragma unroll
        for(int nt = 0; nt < 8; nt++)
          mma_bf16(acc[mt][nt], ahk[mt], &blk[nt>>1][(nt&1)*2]);
      #pragma unroll
      for(int mt = 0; mt < 2; mt++)
        #pragma unroll
        for(int nt = 0; nt < 8; nt++)
          mma_bf16(acc[mt][nt], alk[mt], &bhk[nt>>1][(nt&1)*2]);
    }
  }

  // ---- epilogue ----
  int mrow = lane >> 2;
  int ncol = (lane & 3) * 2;
  #pragma unroll
  for(int mt = 0; mt < 2; mt++){
    #pragma unroll
    for(int nt = 0; nt < 8; nt++){
      #pragma unroll
      for(int hf = 0; hf < 2; hf++){
        long gm = m0 + wm*32 + mt*16 + mrow + hf*8;
        int  gn = n0 + wn*64 + nt*8 + ncol;
        float v0 = acc[mt][nt][hf*2+0];
        float v1 = acc[mt][nt][hf*2+1];
        if(bias){ v0 += bias[gn]; v1 += bias[gn+1]; }
        if(ACT == 1){ v0 = fmaxf(v0,0.f); v1 = fmaxf(v1,0.f); }
        else if(ACT == 2){ v0 = 1.f/(1.f+__expf(-v0)); v1 = 1.f/(1.f+__expf(-v1)); }
        else if(ACT == 3){ v0 = fmaxf(v0,0.f); v0 *= v0; v1 = fmaxf(v1,0.f); v1 *= v1; }
        if(OUT == 0){
          float* cp = C + gm*N + gn;
          if(EPI == 1){ v0 += cp[0]; v1 += cp[1]; }
          else if(EPI == 2){
            const float* mp = mul + gm*N + gn;
            v0 = cp[0] + mp[0]*v0; v1 = cp[1] + mp[1]*v1;
          }
          *(float2*)cp = make_float2(v0, v1);
        } else {
          uint32_t hh, ll;
          split2(v0, v1, hh, ll);
          *(uint32_t*)&Ch[gm*N + gn] = hh;
          *(uint32_t*)&Cl[gm*N + gn] = ll;
        }
      }
    }
  }
}

// ---------------- conv1: direct, (B,1,4096,80) -> (B,2048,40,128) fp32 ------
__global__ void conv1_k(const float* __restrict__ x, const float* __restrict__ w,
                        const float* __restrict__ bias){
  int t = blockIdx.x*256 + threadIdx.x;
  int co = t & 127;
  int rest = t >> 7;
  int wo = rest % W1; rest /= W1;
  int ho = rest % H1; int b = rest / H1;
  float acc = bias[co];
  int hi0 = 2*ho - 1, wi0 = 2*wo - 1;
  #pragma unroll
  for(int kh=0; kh<3; kh++){
    int hi = hi0 + kh;
    if(hi < 0 || hi >= LEN) continue;
    #pragma unroll
    for(int kw=0; kw<3; kw++){
      int wi = wi0 + kw;
      if(wi < 0 || wi >= FREQ) continue;
      acc = fmaf(x[(hi + (long)b*LEN)*FREQ + wi], w[co*9 + kh*3 + kw], acc);
    }
  }
  g_conv1[t] = fmaxf(acc, 0.f);
}

// ---------------- conv weight prep: OIHW -> [co][(r)*CI+ci], split bf16 -----
__global__ void prep_conv_k(const float* __restrict__ w2, const float* __restrict__ w3){
  int t = blockIdx.x*256 + threadIdx.x;
  if(t < C2*K2C){
    int co = t / K2C; int idx = t % K2C;
    int r = idx / C1; int ci = idx % C1;
    float v = w2[co*(C1*9) + ci*9 + r];
    bf h = __float2bfloat16(v);
    g_w2Th[t] = h; g_w2Tl[t] = __float2bfloat16(v - __bfloat162float(h));
  } else {
    int u = t - C2*K2C;
    if(u >= C3*K3C) return;
    int co = u / K3C; int idx = u % K3C;
    int r = idx / C2; int ci = idx % C2;
    float v = w3[co*(C2*9) + ci*9 + r];
    bf h = __float2bfloat16(v);
    g_w3Th[u] = h; g_w3Tl[u] = __float2bfloat16(v - __bfloat162float(h));
  }
}

// ---------------- big weight prep: transpose [R][C]->[C][R] + split ----------
__global__ void prep_big_k(const float* __restrict__ embed_w,
                           const float* __restrict__ awk, const float* __restrict__ awv,
                           const float* __restrict__ awr, const float* __restrict__ awo,
                           const float* __restrict__ fwr, const float* __restrict__ fwk,
                           const float* __restrict__ fwv){
  int t = blockIdx.x;
  const float* in; bf *oh, *ol; int R, C, tr, tc;
  if(t < 5120){
    in = embed_w; oh = g_ewTh; ol = g_ewTl; R = KE; C = DIM;
    tr = t / 16; tc = t % 16;
  } else {
    int u = t - 5120;
    int i = u / 3328; int v = u % 3328;
    long o2 = (long)i*DIM*DIM, oh2 = (long)i*DIM*HID;
    if(v < 1280){
      int kind = v / 256; v %= 256;
      R = DIM; C = DIM; tr = v / 16; tc = v % 16;
      switch(kind){
        case 0: in = awk + o2; oh = g_awkTh + o2; ol = g_awkTl + o2; break;
        case 1: in = awv + o2; oh = g_awvTh + o2; ol = g_awvTl + o2; break;
        case 2: in = awr + o2; oh = g_awrTh + o2; ol = g_awrTl + o2; break;
        case 3: in = awo + o2; oh = g_awoTh + o2; ol = g_awoTl + o2; break;
        default: in = fwr + o2; oh = g_fwrTh + o2; ol = g_fwrTl + o2; break;
      }
    } else {
      v -= 1280;
      if(v < 1024){
        in = fwk + oh2; oh = g_fwkTh + oh2; ol = g_fwkTl + oh2;
        R = DIM; C = HID; tr = v / 64; tc = v % 64;
      } else {
        v -= 1024;
        in = fwv + oh2; oh = g_fwvTh + oh2; ol = g_fwvTl + oh2;
        R = HID; C = DIM; tr = v / 16; tc = v % 16;
      }
    }
  }
  __shared__ float tile[32][33];
  int r0 = tr*32, c0 = tc*32;
  int x = c0 + threadIdx.x;
  for(int dy = threadIdx.y; dy < 32; dy += 8)
    tile[dy][threadIdx.x] = in[(long)(r0 + dy)*C + x];
  __syncthreads();
  int xo = r0 + threadIdx.x;
  for(int dy = threadIdx.y; dy < 32; dy += 8){
    float v = tile[threadIdx.x][dy];
    bf h = __float2bfloat16(v);
    long oidx = (long)(c0 + dy)*R + xo;
    oh[oidx] = h; ol[oidx] = __float2bfloat16(v - __bfloat162float(h));
  }
}

// ---------------- im2col, split output ---------------------------------------
__global__ void im2col2_k(){
  int t = blockIdx.x*256 + threadIdx.x;
  int k4 = t % (K2C/4); int m = t / (K2C/4);
  int k = k4*4;
  int r = k >> 7; int ci = k & 127;
  int kh = r / 3, kw = r % 3;
  int wo = m % W2; int rest = m / W2;
  int ho = rest % H2; int b = rest / H2;
  int hi = 2*ho + kh - 1, wi = 2*wo + kw - 1;
  float4 v = make_float4(0.f,0.f,0.f,0.f);
  if(hi >= 0 && hi < H1 && wi >= 0 && wi < W1)
    v = *(const float4*)&g_conv1[((b*H1 + hi)*W1 + wi)*C1 + ci];
  uint2 hh, ll;
  split4(v, hh, ll);
  long dst = (long)m*K2C + k;
  *(uint2*)&g_col2h[dst] = hh;
  *(uint2*)&g_col2l[dst] = ll;
}
__global__ void im2col3_k(){
  int t = blockIdx.x*256 + threadIdx.x;
  int k4 = t % (K3C/4); int m = t / (K3C/4);
  int k = k4*4;
  int r = k >> 8; int ci = k & 255;
  int kh = r / 3, kw = r % 3;
  int wo = m % W2; int rest = m / W2;
  int ho = rest % H2; int b = rest / H2;
  int hi = ho + kh - 1, wi = wo + kw - 1;
  uint2 vh = make_uint2(0,0), vl = make_uint2(0,0);
  if(hi >= 0 && hi < H2 && wi >= 0 && wi < W2){
    long src = (long)((b*H2 + hi)*W2 + wi)*C2 + ci;
    vh = *(const uint2*)&g_c2h[src];
    vl = *(const uint2*)&g_c2l[src];
  }
  long dst = (long)m*K3C + k;
  *(uint2*)&g_col3h[dst] = vh;
  *(uint2*)&g_col3l[dst] = vl;
}

// ---------------- reshape (b,u,w,c) -> (b,u, c*20+w), bf16 pair ---------------
__global__ void reshape_k(){
  __shared__ uint16_t smh[KE], sml[KE];
  int m = blockIdx.x;
  const uint16_t* srch = (const uint16_t*)g_c3h + (long)m*KE;
  const uint16_t* srcl = (const uint16_t*)g_c3l + (long)m*KE;
  for(int i=threadIdx.x; i<KE; i+=256){
    int w = i / 512, c = i & 511;
    int d = c*W2 + w;
    smh[d] = srch[i];
    sml[d] = srcl[i];
  }
  __syncthreads();
  uint16_t* dsth = (uint16_t*)g_yrh + (long)m*KE;
  uint16_t* dstl = (uint16_t*)g_yrl + (long)m*KE;
  for(int i=threadIdx.x; i<KE; i+=256){ dsth[i] = smh[i]; dstl[i] = sml[i]; }
}

// ---------------- LayerNorm over D=512, 128 threads per token ----------------
__global__ void ln_k(const float* __restrict__ x, const float* __restrict__ gw,
                     const float* __restrict__ gb, float* __restrict__ o){
  int m = blockIdx.x;
  int tid = threadIdx.x;
  const float* xr = x + (long)m*DIM;
  float v[4]; float s = 0.f, sq = 0.f;
  #pragma unroll
  for(int j=0;j<4;j++){ float t = xr[tid + j*128]; v[j] = t; s += t; sq += t*t; }
  #pragma unroll
  for(int off=16; off; off>>=1){
    s  += __shfl_xor_sync(0xffffffffu, s,  off);
    sq += __shfl_xor_sync(0xffffffffu, sq, off);
  }
  __shared__ float ss[4], sqs[4];
  if((tid & 31) == 0){ ss[tid>>5] = s; sqs[tid>>5] = sq; }
  __syncthreads();
  s  = (ss[0]+ss[1]) + (ss[2]+ss[3]);
  sq = (sqs[0]+sqs[1]) + (sqs[2]+sqs[3]);
  float mean = s * (1.f/DIM);
  float var  = sq * (1.f/DIM) - mean*mean;
  float rstd = rsqrtf(var + 1e-5f);
  float* orow = o + (long)m*DIM;
  #pragma unroll
  for(int j=0;j<4;j++){
    int d = tid + j*128;
    orow[d] = (v[j] - mean)*rstd*gw[d] + gb[d];
  }
}

// ---------------- time-shift mixes (emit bf16 hi/lo) --------------------------
__global__ void mix3_k(const float* __restrict__ xn, const float* __restrict__ mk,
                       const float* __restrict__ mv, const float* __restrict__ mr){
  int g = blockIdx.x*256 + threadIdx.x;
  int t = g*2;
  int d = t & (DIM-1);
  int tok = (t >> 9) & (USEQ-1);
  float2 cur = *(const float2*)&xn[t];
  float2 sh = tok ? *(const float2*)&xn[t - DIM] : make_float2(0.f, 0.f);
  float d0 = cur.x - sh.x, d1 = cur.y - sh.y;
  uint32_t h, l;
  split2(fmaf(d0, mk[d], sh.x), fmaf(d1, mk[d+1], sh.y), h, l);
  *(uint32_t*)&g_xkh[t] = h; *(uint32_t*)&g_xkl[t] = l;
  split2(fmaf(d0, mv[d], sh.x), fmaf(d1, mv[d+1], sh.y), h, l);
  *(uint32_t*)&g_xvh[t] = h; *(uint32_t*)&g_xvl[t] = l;
  split2(fmaf(d0, mr[d], sh.x), fmaf(d1, mr[d+1], sh.y), h, l);
  *(uint32_t*)&g_xrh[t] = h; *(uint32_t*)&g_xrl[t] = l;
}
__global__ void mix2_k(const float* __restrict__ xn, const float* __restrict__ mk,
                       const float* __restrict__ mr){
  int g = blockIdx.x*256 + threadIdx.x;
  int t = g*2;
  int d = t & (DIM-1);
  int tok = (t >> 9) & (USEQ-1);
  float2 cur = *(const float2*)&xn[t];
  float2 sh = tok ? *(const float2*)&xn[t - DIM] : make_float2(0.f, 0.f);
  float d0 = cur.x - sh.x, d1 = cur.y - sh.y;
  uint32_t h, l;
  split2(fmaf(d0, mk[d], sh.x), fmaf(d1, mk[d+1], sh.y), h, l);
  *(uint32_t*)&g_xkh[t] = h; *(uint32_t*)&g_xkl[t] = l;
  split2(fmaf(d0, mr[d], sh.x), fmaf(d1, mr[d+1], sh.y), h, l);
  *(uint32_t*)&g_xrh[t] = h; *(uint32_t*)&g_xrl[t] = l;
}

// ---------------- WKV scan, pipelined, bf16 split output ----------------------
#define WG 8
__device__ __forceinline__ void wkv_load(const float* kp, const float* vp,
                                         const float* rp, long off0,
                                         float* kb, float* vb, float* rb){
  #pragma unroll
  for(int j=0;j<WG;j++){
    long off = off0 + (long)j*DIM;
    kb[j] = __ldg(kp + off); vb[j] = __ldg(vp + off); rb[j] = __ldg(rp + off);
  }
}
__device__ __forceinline__ void wkv_step(float* kb, float* vb, float* rb,
                                         bf* oh, bf* ol, long off0,
                                         float w, float u,
                                         float& aa, float& bb, float& pp){
  #pragma unroll
  for(int j=0;j<WG;j++){
    float kt = kb[j], vt = vb[j];
    float ww = u + kt;
    float p  = fmaxf(pp, ww);
    float e1 = __expf(pp - p), e2 = __expf(ww - p);
    float o  = rb[j] * (e1*aa + e2*vt) / (e1*bb + e2);
    bf h = __float2bfloat16(o);
    long off = off0 + (long)j*DIM;
    oh[off] = h;
    ol[off] = __float2bfloat16(o - __bfloat162float(h));
    float ww2 = pp + w;
    float p2  = fmaxf(ww2, kt);
    e1 = __expf(ww2 - p2); e2 = __expf(kt - p2);
    aa = e1*aa + e2*vt; bb = e1*bb + e2; pp = p2;
  }
}
__global__ void wkv_k(const float* __restrict__ k, const float* __restrict__ v,
                      const float* __restrict__ r,
                      const float* __restrict__ dec, const float* __restrict__ fir){
  int t = blockIdx.x*blockDim.x + threadIdx.x;
  int d = t & (DIM-1); int b = t >> 9;
  float w = -__expf(dec[d]);
  float u = fir[d];
  float aa = 0.f, bb = 0.f, pp = -1e38f;
  long base = (long)b*USEQ*DIM + d;
  const float* kp = k + base;
  const float* vp = v + base;
  const float* rp = r + base;
  bf* oh = g_rwh + base;
  bf* ol = g_rwl + base;
  const int NG = USEQ/WG;
  float k0b[WG], v0b[WG], r0b[WG];
  float k1b[WG], v1b[WG], r1b[WG];
  wkv_load(kp, vp, rp, 0, k0b, v0b, r0b);
  for(int g=0; g<NG; g+=2){
    long off1 = (long)(g+1)*WG*DIM;
    wkv_load(kp, vp, rp, off1, k1b, v1b, r1b);
    wkv_step(k0b, v0b, r0b, oh, ol, (long)g*WG*DIM, w, u, aa, bb, pp);
    if(g+2 < NG){
      long off2 = (long)(g+2)*WG*DIM;
      wkv_load(kp, vp, rp, off2, k0b, v0b, r0b);
    }
    wkv_step(k1b, v1b, r1b, oh, ol, off1, w, u, aa, bb, pp);
  }
}

// ---------------- olens tail --------------------------------------------------
__global__ void tail_k(const int* __restrict__ x_len, float* __restrict__ out, int out_size){
  int b = threadIdx.x;
  if(b < BATCH && out_size >= HTOK + BATCH){
    int l1 = (x_len[b] - 1)/2 + 1;
    int ol = (l1 - 1)/2 + 1;
    out[HTOK + b] = (float)ol;
  }
}

// ---------------- host side ---------------------------------------------------
template <typename T>
static void* symaddr(const T& s){ void* p = nullptr; cudaGetSymbolAddress(&p, s); return p; }

template<int ACT, int EPI, int OUT>
static void gemm(int M, int N, int K, const bf* Ah, const bf* Al,
                 const bf* Bh, const bf* Bl, const float* bias,
                 float* C, bf* Ch, bf* Cl, const float* mul){
  cudaFuncSetAttribute(mgemm_k<ACT,EPI,OUT>, cudaFuncAttributeMaxDynamicSharedMemorySize, MSMEM);
  dim3 grid(N/128, M/128);
  mgemm_k<ACT,EPI,OUT><<<grid, 256, MSMEM>>>(M, N, K, Ah, Al, Bh, Bl, bias, C, Ch, Cl, mul);
}

extern "C" void kernel_launch(void* const* d_in, const int* in_sizes, int n_in,
                              void* d_out, int out_size){
  const float* x       = (const float*)d_in[0];
  const int*   x_len   = (const int*)  d_in[1];
  const float* conv1_w = (const float*)d_in[2];
  const float* conv1_b = (const float*)d_in[3];
  const float* conv2_w = (const float*)d_in[4];
  const float* conv2_b = (const float*)d_in[5];
  const float* conv3_w = (const float*)d_in[6];
  const float* conv3_b = (const float*)d_in[7];
  const float* embed_w = (const float*)d_in[8];
  const float* embed_b = (const float*)d_in[9];
  const float* eln_g   = (const float*)d_in[10];
  const float* eln_b   = (const float*)d_in[11];
  const float* lag     = (const float*)d_in[12];
  const float* lab     = (const float*)d_in[13];
  const float* dec     = (const float*)d_in[14];
  const float* fir     = (const float*)d_in[15];
  const float* amk     = (const float*)d_in[16];
  const float* amv     = (const float*)d_in[17];
  const float* amr     = (const float*)d_in[18];
  const float* awk     = (const float*)d_in[19];
  const float* awv     = (const float*)d_in[20];
  const float* awr     = (const float*)d_in[21];
  const float* awo     = (const float*)d_in[22];
  const float* lfg     = (const float*)d_in[23];
  const float* lfb     = (const float*)d_in[24];
  const float* fmk     = (const float*)d_in[25];
  const float* fmr     = (const float*)d_in[26];
  const float* fwk     = (const float*)d_in[27];
  const float* fwv     = (const float*)d_in[28];
  const float* fwr     = (const float*)d_in[29];
  const float* flg     = (const float*)d_in[30];
  const float* flb     = (const float*)d_in[31];
  float* out = (float*)d_out;

  bf* p_col2h = (bf*)symaddr(g_col2h); bf* p_col2l = (bf*)symaddr(g_col2l);
  bf* p_c2h   = (bf*)symaddr(g_c2h);   bf* p_c2l   = (bf*)symaddr(g_c2l);
  bf* p_col3h = (bf*)symaddr(g_col3h); bf* p_col3l = (bf*)symaddr(g_col3l);
  bf* p_c3h   = (bf*)symaddr(g_c3h);   bf* p_c3l   = (bf*)symaddr(g_c3l);
  bf* p_yrh   = (bf*)symaddr(g_yrh);   bf* p_yrl   = (bf*)symaddr(g_yrl);
  float* p_t0 = (float*)symaddr(g_t0);
  float* p_h  = (float*)symaddr(g_h);
  float* p_xn = (float*)symaddr(g_xn);
  bf* p_xkh = (bf*)symaddr(g_xkh); bf* p_xkl = (bf*)symaddr(g_xkl);
  bf* p_xvh = (bf*)symaddr(g_xvh); bf* p_xvl = (bf*)symaddr(g_xvl);
  bf* p_xrh = (bf*)symaddr(g_xrh); bf* p_xrl = (bf*)symaddr(g_xrl);
  float* p_k = (float*)symaddr(g_k);
  float* p_v = (float*)symaddr(g_v);
  float* p_r = (float*)symaddr(g_r);
  bf* p_rwh = (bf*)symaddr(g_rwh); bf* p_rwl = (bf*)symaddr(g_rwl);
  bf* p_kkh = (bf*)symaddr(g_kkh); bf* p_kkl = (bf*)symaddr(g_kkl);
  bf* p_w2Th = (bf*)symaddr(g_w2Th); bf* p_w2Tl = (bf*)symaddr(g_w2Tl);
  bf* p_w3Th = (bf*)symaddr(g_w3Th); bf* p_w3Tl = (bf*)symaddr(g_w3Tl);
  bf* p_ewTh = (bf*)symaddr(g_ewTh); bf* p_ewTl = (bf*)symaddr(g_ewTl);
  bf* p_awkTh = (bf*)symaddr(g_awkTh); bf* p_awkTl = (bf*)symaddr(g_awkTl);
  bf* p_awvTh = (bf*)symaddr(g_awvTh); bf* p_awvTl = (bf*)symaddr(g_awvTl);
  bf* p_awrTh = (bf*)symaddr(g_awrTh); bf* p_awrTl = (bf*)symaddr(g_awrTl);
  bf* p_awoTh = (bf*)symaddr(g_awoTh); bf* p_awoTl = (bf*)symaddr(g_awoTl);
  bf* p_fwkTh = (bf*)symaddr(g_fwkTh); bf* p_fwkTl = (bf*)symaddr(g_fwkTl);
  bf* p_fwvTh = (bf*)symaddr(g_fwvTh); bf* p_fwvTl = (bf*)symaddr(g_fwvTl);
  bf* p_fwrTh = (bf*)symaddr(g_fwrTh); bf* p_fwrTl = (bf*)symaddr(g_fwrTl);

  // launches 1-6 (launch 6 = conv3 GEMM gets profiled by ncu -s 5 -c 1)
  prep_conv_k<<<(C2*K2C + C3*K3C + 255)/256, 256>>>(conv2_w, conv3_w);
  conv1_k<<<(BATCH*H1*W1*C1)/256, 256>>>(x, conv1_w, conv1_b);
  im2col2_k<<<(MCONV*(K2C/4))/256, 256>>>();
  gemm<1,0,1>(MCONV, C2, K2C, p_col2h, p_col2l, p_w2Th, p_w2Tl, conv2_b,
              nullptr, p_c2h, p_c2l, nullptr);
  im2col3_k<<<(MCONV*(K3C/4))/256, 256>>>();
  gemm<1,0,1>(MCONV, C3, K3C, p_col3h, p_col3l, p_w3Th, p_w3Tl, conv3_b,
              nullptr, p_c3h, p_c3l, nullptr);

  prep_big_k<<<18432, dim3(32,8)>>>(embed_w, awk, awv, awr, awo, fwr, fwk, fwv);
  reshape_k<<<MT, 256>>>();
  gemm<0,0,0>(MT, DIM, KE, p_yrh, p_yrl, p_ewTh, p_ewTl, embed_b,
              p_t0, nullptr, nullptr, nullptr);
  ln_k<<<MT, 128>>>(p_t0, eln_g, eln_b, p_h);

  // ---- RWKV blocks ----
  for(int i = 0; i < NB_; i++){
    long w2 = (long)i*DIM*DIM;
    long wh = (long)i*DIM*HID;
    // time mixing
    ln_k<<<MT, 128>>>(p_h, lag + i*DIM, lab + i*DIM, p_xn);
    mix3_k<<<HTOK/512, 256>>>(p_xn, amk + i*DIM, amv + i*DIM, amr + i*DIM);
    gemm<0,0,0>(MT, DIM, DIM, p_xkh, p_xkl, p_awkTh + w2, p_awkTl + w2, nullptr,
                p_k, nullptr, nullptr, nullptr);
    gemm<0,0,0>(MT, DIM, DIM, p_xvh, p_xvl, p_awvTh + w2, p_awvTl + w2, nullptr,
                p_v, nullptr, nullptr, nullptr);
    gemm<2,0,0>(MT, DIM, DIM, p_xrh, p_xrl, p_awrTh + w2, p_awrTl + w2, nullptr,
                p_r, nullptr, nullptr, nullptr);
    wkv_k<<<(BATCH*DIM)/256, 256>>>(p_k, p_v, p_r, dec + i*DIM, fir + i*DIM);
    gemm<0,1,0>(MT, DIM, DIM, p_rwh, p_rwl, p_awoTh + w2, p_awoTl + w2, nullptr,
                p_h, nullptr, nullptr, nullptr);
    // channel mixing
    ln_k<<<MT, 128>>>(p_h, lfg + i*DIM, lfb + i*DIM, p_xn);
    mix2_k<<<HTOK/512, 256>>>(p_xn, fmk + i*DIM, fmr + i*DIM);
    gemm<3,0,1>(MT, HID, DIM, p_xkh, p_xkl, p_fwkTh + wh, p_fwkTl + wh, nullptr,
                nullptr, p_kkh, p_kkl, nullptr);
    gemm<2,0,0>(MT, DIM, DIM, p_xrh, p_xrl, p_fwrTh + w2, p_fwrTl + w2, nullptr,
                p_r, nullptr, nullptr, nullptr);
    gemm<0,2,0>(MT, DIM, HID, p_kkh, p_kkl, p_fwvTh + wh, p_fwvTl + wh, nullptr,
                p_h, nullptr, nullptr, p_r);
  }

  ln_k<<<MT, 128>>>(p_h, flg, flb, out);
  tail_k<<<1, 32>>>(x_len, out, out_size);
}

// round 8
// speedup vs baseline: 2.3711x; 1.0033x over previous
#include <cuda_runtime.h>
#include <cuda_bf16.h>
#include <cstdint>

typedef __nv_bfloat16 bf;

#define NB_   4
#define BATCH 8
#define LEN   4096
#define FREQ  80
#define DIM   512
#define HID   2048
#define USEQ  1024
#define C1    128
#define C2    256
#define C3    512
#define H1    2048
#define W1    40
#define H2    1024
#define W2    20
#define MCONV (BATCH*H2*W2)      /* 163840 */
#define K2C   (9*C1)             /* 1152 */
#define K3C   (9*C2)             /* 2304 */
#define KE    (C3*W2)            /* 10240 */
#define MT    (BATCH*USEQ)       /* 8192 */
#define HTOK  (MT*DIM)           /* 4194304 */

// ---------------- scratch (device globals; no allocations) ----------------
__device__ float g_conv1[BATCH*H1*W1*C1];
__device__ bf g_col2h[MCONV*K2C],  g_col2l[MCONV*K2C];
__device__ bf g_c2h[MCONV*C2],     g_c2l[MCONV*C2];
__device__ bf g_col3h[MCONV*K3C],  g_col3l[MCONV*K3C];
__device__ bf g_c3h[MCONV*C3],     g_c3l[MCONV*C3];
__device__ bf g_yrh[MT*KE],        g_yrl[MT*KE];
__device__ float g_t0[HTOK];
__device__ float g_h[HTOK];
__device__ float g_xn[HTOK];
__device__ bf g_xkh[HTOK], g_xkl[HTOK];
__device__ bf g_xvh[HTOK], g_xvl[HTOK];
__device__ bf g_xrh[HTOK], g_xrl[HTOK];
__device__ float g_k[HTOK];
__device__ float g_v[HTOK];
__device__ float g_r[HTOK];
__device__ bf g_rwh[HTOK], g_rwl[HTOK];
__device__ bf g_kkh[MT*HID], g_kkl[MT*HID];
// transposed+split weights, [N][K] K-major bf16 hi/lo
__device__ bf g_w2Th[C2*K2C],  g_w2Tl[C2*K2C];
__device__ bf g_w3Th[C3*K3C],  g_w3Tl[C3*K3C];
__device__ bf g_ewTh[DIM*KE],  g_ewTl[DIM*KE];
__device__ bf g_aqkvTh[NB_*3*DIM*DIM], g_aqkvTl[NB_*3*DIM*DIM];   // [wk|wv|wr]^T
__device__ bf g_awoTh[NB_*DIM*DIM],    g_awoTl[NB_*DIM*DIM];
__device__ bf g_fkrTh[NB_*(HID+DIM)*DIM], g_fkrTl[NB_*(HID+DIM)*DIM]; // [fwk|fwr]^T
__device__ bf g_fwvTh[NB_*DIM*HID],    g_fwvTl[NB_*DIM*HID];

// ================== helpers ==================
__device__ __forceinline__ uint32_t smem_to_u32(const void* p) {
  uint32_t a;
  asm("{ .reg .u64 t; cvta.to.shared.u64 t, %1; cvt.u32.u64 %0, t; }"
      : "=r"(a) : "l"(p));
  return a;
}
__device__ __forceinline__ void ldsm4(uint32_t* r, uint32_t addr){
  asm volatile("ldmatrix.sync.aligned.m8n8.x4.shared.b16 {%0,%1,%2,%3}, [%4];"
    : "=r"(r[0]),"=r"(r[1]),"=r"(r[2]),"=r"(r[3]) : "r"(addr));
}
__device__ __forceinline__ void mma_bf16(float* d, const uint32_t* a, const uint32_t* b){
  asm volatile("mma.sync.aligned.m16n8k16.row.col.f32.bf16.bf16.f32 "
    "{%0,%1,%2,%3}, {%4,%5,%6,%7}, {%8,%9}, {%0,%1,%2,%3};"
    : "+f"(d[0]),"+f"(d[1]),"+f"(d[2]),"+f"(d[3])
    : "r"(a[0]),"r"(a[1]),"r"(a[2]),"r"(a[3]), "r"(b[0]),"r"(b[1]));
}
__device__ __forceinline__ void cp16(uint32_t s, const void* g){
  asm volatile("cp.async.cg.shared.global [%0], [%1], 16;" :: "r"(s), "l"(g));
}
#define CP_COMMIT() asm volatile("cp.async.commit_group;" ::: "memory")
#define CP_WAIT1()  asm volatile("cp.async.wait_group 1;" ::: "memory")

__device__ __forceinline__ void split2(float v0, float v1, uint32_t& h, uint32_t& l){
  __nv_bfloat162 hh = __floats2bfloat162_rn(v0, v1);
  float r0 = v0 - __bfloat162float(hh.x);
  float r1 = v1 - __bfloat162float(hh.y);
  __nv_bfloat162 ll = __floats2bfloat162_rn(r0, r1);
  h = *(uint32_t*)&hh; l = *(uint32_t*)&ll;
}
__device__ __forceinline__ void split4(float4 v, uint2& hi, uint2& lo){
  split2(v.x, v.y, hi.x, lo.x);
  split2(v.z, v.w, hi.y, lo.y);
}
__device__ __forceinline__ float sgm(float v){ return 1.f/(1.f + __expf(-v)); }

// ====== bf16x3 MMA GEMM: CTA 128x128, Kchunk=32, 8 warps, cp.async 3-stage ===
// C = epi(act(A @ Wt^T + bias))
// ACT: 0 none,1 relu,2 sigmoid,3 relu^2 ; EPI: 0 store,1 +=,2 C+mul*acc
// OUT: 0 fp32 C ; 1 bf16 split Ch/Cl
#define PITCH 40
#define AHI_O 0
#define ALO_O 10240
#define BHI_O 20480
#define BLO_O 30720
#define STG_B 40960
#define MSMEM (3*STG_B)

template<int ACT, int EPI, int OUT>
__global__ void __launch_bounds__(256, 1) mgemm_k(int M, int N, int K,
    const bf* __restrict__ Ah, const bf* __restrict__ Al,
    const bf* __restrict__ Bh, const bf* __restrict__ Bl,
    const float* __restrict__ bias, float* __restrict__ C,
    bf* __restrict__ Ch, bf* __restrict__ Cl, const float* __restrict__ mul){
  extern __shared__ char smarr[];
  uint32_t smb = smem_to_u32(smarr);
  int tid = threadIdx.x, lane = tid & 31, wid = tid >> 5;
  int wm = wid >> 1, wn = wid & 1;
  long m0 = (long)blockIdx.y * 128;
  int  n0 = blockIdx.x * 128;

  int lrow = tid >> 1;
  long lga = (m0 + lrow)*(long)K + (tid & 1)*16;
  long lgb = ((long)n0 + lrow)*K + (tid & 1)*16;
  uint32_t lso = (uint32_t)lrow*80 + (tid & 1)*32;

  uint32_t aoff = (((uint32_t)wm*32 + ((lane>>3)&1)*8 + (lane&7))*PITCH + ((lane>>4)&1)*8) * 2;
  uint32_t boff = (((uint32_t)wn*64 + ((lane>>4)&1)*8 + (lane&7))*PITCH + ((lane>>3)&1)*8) * 2;

  float acc[2][8][4];
  #pragma unroll
  for(int i=0;i<2;i++)
    #pragma unroll
    for(int j=0;j<8;j++)
      #pragma unroll
      for(int q=0;q<4;q++) acc[i][j][q] = 0.f;

  int nc = K >> 5;

  #define LOAD_CHUNK(c, sidx) do { \
    uint32_t stg_ = smb + (sidx)*STG_B; \
    long go_ = (long)(c)*32; \
    cp16(stg_ + AHI_O + lso,      Ah + lga + go_); \
    cp16(stg_ + AHI_O + lso + 16, Ah + lga + go_ + 8); \
    cp16(stg_ + ALO_O + lso,      Al + lga + go_); \
    cp16(stg_ + ALO_O + lso + 16, Al + lga + go_ + 8); \
    cp16(stg_ + BHI_O + lso,      Bh + lgb + go_); \
    cp16(stg_ + BHI_O + lso + 16, Bh + lgb + go_ + 8); \
    cp16(stg_ + BLO_O + lso,      Bl + lgb + go_); \
    cp16(stg_ + BLO_O + lso + 16, Bl + lgb + go_ + 8); \
  } while(0)

  LOAD_CHUNK(0, 0); CP_COMMIT();
  LOAD_CHUNK(1, 1); CP_COMMIT();

  for(int c = 0; c < nc; c++){
    CP_WAIT1();
    __syncthreads();
    if(c + 2 < nc){ LOAD_CHUNK(c + 2, (c + 2) % 3); }
    CP_COMMIT();
    uint32_t stg = smb + (c % 3)*STG_B;
    #pragma unroll
    for(int ks = 0; ks < 2; ks++){
      uint32_t ahk[2][4], alk[2][4], bhk[4][4], blk[4][4];
      #pragma unroll
      for(int mt = 0; mt < 2; mt++){
        uint32_t ad = stg + AHI_O + aoff + mt*(16*PITCH*2) + ks*32;
        ldsm4(ahk[mt], ad);
        ldsm4(alk[mt], ad + (ALO_O - AHI_O));
      }
      #pragma unroll
      for(int ng = 0; ng < 4; ng++){
        uint32_t bd = stg + BHI_O + boff + ng*(16*PITCH*2) + ks*32;
        ldsm4(bhk[ng], bd);
        ldsm4(blk[ng], bd + (BLO_O - BHI_O));
      }
      #pragma unroll
      for(int mt = 0; mt < 2; mt++)
        #pragma unroll
        for(int nt = 0; nt < 8; nt++)
          mma_bf16(acc[mt][nt], ahk[mt], &bhk[nt>>1][(nt&1)*2]);
      #pragma unroll
      for(int mt = 0; mt < 2; mt++)
        #pragma unroll
        for(int nt = 0; nt < 8; nt++)
          mma_bf16(acc[mt][nt], ahk[mt], &blk[nt>>1][(nt&1)*2]);
      #pragma unroll
      for(int mt = 0; mt < 2; mt++)
        #pragma unroll
        for(int nt = 0; nt < 8; nt++)
          mma_bf16(acc[mt][nt], alk[mt], &bhk[nt>>1][(nt&1)*2]);
    }
  }

  // ---- epilogue ----
  int mrow = lane >> 2;
  int ncol = (lane & 3) * 2;
  #pragma unroll
  for(int mt = 0; mt < 2; mt++){
    #pragma unroll
    for(int nt = 0; nt < 8; nt++){
      #pragma unroll
      for(int hf = 0; hf < 2; hf++){
        long gm = m0 + wm*32 + mt*16 + mrow + hf*8;
        int  gn = n0 + wn*64 + nt*8 + ncol;
        float v0 = acc[mt][nt][hf*2+0];
        float v1 = acc[mt][nt][hf*2+1];
        if(bias){ v0 += bias[gn]; v1 += bias[gn+1]; }
        if(ACT == 1){ v0 = fmaxf(v0,0.f); v1 = fmaxf(v1,0.f); }
        else if(ACT == 2){ v0 = sgm(v0); v1 = sgm(v1); }
        else if(ACT == 3){ v0 = fmaxf(v0,0.f); v0 *= v0; v1 = fmaxf(v1,0.f); v1 *= v1; }
        if(OUT == 0){
          float* cp = C + gm*N + gn;
          if(EPI == 1){ v0 += cp[0]; v1 += cp[1]; }
          else if(EPI == 2){
            const float* mp = mul + gm*N + gn;
            v0 = cp[0] + mp[0]*v0; v1 = cp[1] + mp[1]*v1;
          }
          *(float2*)cp = make_float2(v0, v1);
        } else {
          uint32_t hh, ll;
          split2(v0, v1, hh, ll);
          *(uint32_t*)&Ch[gm*N + gn] = hh;
          *(uint32_t*)&Cl[gm*N + gn] = ll;
        }
      }
    }
  }
}

// ---------------- conv1 ------------------------------------------------------
__global__ void conv1_k(const float* __restrict__ x, const float* __restrict__ w,
                        const float* __restrict__ bias){
  int t = blockIdx.x*256 + threadIdx.x;
  int co = t & 127;
  int rest = t >> 7;
  int wo = rest % W1; rest /= W1;
  int ho = rest % H1; int b = rest / H1;
  float acc = bias[co];
  int hi0 = 2*ho - 1, wi0 = 2*wo - 1;
  #pragma unroll
  for(int kh=0; kh<3; kh++){
    int hi = hi0 + kh;
    if(hi < 0 || hi >= LEN) continue;
    #pragma unroll
    for(int kw=0; kw<3; kw++){
      int wi = wi0 + kw;
      if(wi < 0 || wi >= FREQ) continue;
      acc = fmaf(x[(hi + (long)b*LEN)*FREQ + wi], w[co*9 + kh*3 + kw], acc);
    }
  }
  g_conv1[t] = fmaxf(acc, 0.f);
}

// ---------------- conv weight prep -------------------------------------------
__global__ void prep_conv_k(const float* __restrict__ w2, const float* __restrict__ w3){
  int t = blockIdx.x*256 + threadIdx.x;
  if(t < C2*K2C){
    int co = t / K2C; int idx = t % K2C;
    int r = idx / C1; int ci = idx % C1;
    float v = w2[co*(C1*9) + ci*9 + r];
    bf h = __float2bfloat16(v);
    g_w2Th[t] = h; g_w2Tl[t] = __float2bfloat16(v - __bfloat162float(h));
  } else {
    int u = t - C2*K2C;
    if(u >= C3*K3C) return;
    int co = u / K3C; int idx = u % K3C;
    int r = idx / C2; int ci = idx % C2;
    float v = w3[co*(C2*9) + ci*9 + r];
    bf h = __float2bfloat16(v);
    g_w3Th[u] = h; g_w3Tl[u] = __float2bfloat16(v - __bfloat162float(h));
  }
}

// ------ big weight prep: transpose [R][C]->[C][R] + split + concat -----------
__global__ void prep_big_k(const float* __restrict__ embed_w,
                           const float* __restrict__ awk, const float* __restrict__ awv,
                           const float* __restrict__ awr, const float* __restrict__ awo,
                           const float* __restrict__ fwr, const float* __restrict__ fwk,
                           const float* __restrict__ fwv){
  int t = blockIdx.x;
  const float* in; bf *oh, *ol; int R, C, tr, tc;
  if(t < 5120){
    in = embed_w; oh = g_ewTh; ol = g_ewTl; R = KE; C = DIM;
    tr = t / 16; tc = t % 16;
  } else {
    int u = t - 5120;
    int i = u / 3328; int v = u % 3328;
    long o2 = (long)i*DIM*DIM, oh2 = (long)i*DIM*HID;
    long qb = (long)i*3*DIM*DIM, fb = (long)i*(HID+DIM)*DIM;
    if(v < 768){
      int kind = v / 256; int vv = v % 256;
      R = DIM; C = DIM; tr = vv / 16; tc = vv % 16;
      in = (kind == 0 ? awk : kind == 1 ? awv : awr) + o2;
      oh = g_aqkvTh + qb + (long)kind*DIM*DIM;
      ol = g_aqkvTl + qb + (long)kind*DIM*DIM;
    } else if(v < 1024){
      int vv = v - 768;
      R = DIM; C = DIM; tr = vv / 16; tc = vv % 16;
      in = awo + o2; oh = g_awoTh + o2; ol = g_awoTl + o2;
    } else if(v < 2048){
      int vv = v - 1024;
      R = DIM; C = HID; tr = vv / 64; tc = vv % 64;
      in = fwk + oh2; oh = g_fkrTh + fb; ol = g_fkrTl + fb;
    } else if(v < 2304){
      int vv = v - 2048;
      R = DIM; C = DIM; tr = vv / 16; tc = vv % 16;
      in = fwr + o2;
      oh = g_fkrTh + fb + (long)HID*DIM;
      ol = g_fkrTl + fb + (long)HID*DIM;
    } else {
      int vv = v - 2304;
      R = HID; C = DIM; tr = vv / 16; tc = vv % 16;
      in = fwv + oh2; oh = g_fwvTh + oh2; ol = g_fwvTl + oh2;
    }
  }
  __shared__ float tile[32][33];
  int r0 = tr*32, c0 = tc*32;
  int x = c0 + threadIdx.x;
  for(int dy = threadIdx.y; dy < 32; dy += 8)
    tile[dy][threadIdx.x] = in[(long)(r0 + dy)*C + x];
  __syncthreads();
  int xo = r0 + threadIdx.x;
  for(int dy = threadIdx.y; dy < 32; dy += 8){
    float v = tile[threadIdx.x][dy];
    bf h = __float2bfloat16(v);
    long oidx = (long)(c0 + dy)*R + xo;
    oh[oidx] = h; ol[oidx] = __float2bfloat16(v - __bfloat162float(h));
  }
}

// ---------------- im2col, split output ---------------------------------------
__global__ void im2col2_k(){
  int t = blockIdx.x*256 + threadIdx.x;
  int k4 = t % (K2C/4); int m = t / (K2C/4);
  int k = k4*4;
  int r = k >> 7; int ci = k & 127;
  int kh = r / 3, kw = r % 3;
  int wo = m % W2; int rest = m / W2;
  int ho = rest % H2; int b = rest / H2;
  int hi = 2*ho + kh - 1, wi = 2*wo + kw - 1;
  float4 v = make_float4(0.f,0.f,0.f,0.f);
  if(hi >= 0 && hi < H1 && wi >= 0 && wi < W1)
    v = *(const float4*)&g_conv1[((b*H1 + hi)*W1 + wi)*C1 + ci];
  uint2 hh, ll;
  split4(v, hh, ll);
  long dst = (long)m*K2C + k;
  *(uint2*)&g_col2h[dst] = hh;
  *(uint2*)&g_col2l[dst] = ll;
}
__global__ void im2col3_k(){
  int t = blockIdx.x*256 + threadIdx.x;
  int k4 = t % (K3C/4); int m = t / (K3C/4);
  int k = k4*4;
  int r = k >> 8; int ci = k & 255;
  int kh = r / 3, kw = r % 3;
  int wo = m % W2; int rest = m / W2;
  int ho = rest % H2; int b = rest / H2;
  int hi = ho + kh - 1, wi = wo + kw - 1;
  uint2 vh = make_uint2(0,0), vl = make_uint2(0,0);
  if(hi >= 0 && hi < H2 && wi >= 0 && wi < W2){
    long src = (long)((b*H2 + hi)*W2 + wi)*C2 + ci;
    vh = *(const uint2*)&g_c2h[src];
    vl = *(const uint2*)&g_c2l[src];
  }
  long dst = (long)m*K3C + k;
  *(uint2*)&g_col3h[dst] = vh;
  *(uint2*)&g_col3l[dst] = vl;
}

// ---------------- reshape ------------------------------------------------------
__global__ void reshape_k(){
  __shared__ uint16_t smh[KE], sml[KE];
  int m = blockIdx.x;
  const uint16_t* srch = (const uint16_t*)g_c3h + (long)m*KE;
  const uint16_t* srcl = (const uint16_t*)g_c3l + (long)m*KE;
  for(int i=threadIdx.x; i<KE; i+=256){
    int w = i / 512, c = i & 511;
    int d = c*W2 + w;
    smh[d] = srch[i];
    sml[d] = srcl[i];
  }
  __syncthreads();
  uint16_t* dsth = (uint16_t*)g_yrh + (long)m*KE;
  uint16_t* dstl = (uint16_t*)g_yrl + (long)m*KE;
  for(int i=threadIdx.x; i<KE; i+=256){ dsth[i] = smh[i]; dstl[i] = sml[i]; }
}

// ---------------- LayerNorm ----------------------------------------------------
__global__ void ln_k(const float* __restrict__ x, const float* __restrict__ gw,
                     const float* __restrict__ gb, float* __restrict__ o){
  int m = blockIdx.x;
  int tid = threadIdx.x;
  const float* xr = x + (long)m*DIM;
  float v[4]; float s = 0.f, sq = 0.f;
  #pragma unroll
  for(int j=0;j<4;j++){ float t = xr[tid + j*128]; v[j] = t; s += t; sq += t*t; }
  #pragma unroll
  for(int off=16; off; off>>=1){
    s  += __shfl_xor_sync(0xffffffffu, s,  off);
    sq += __shfl_xor_sync(0xffffffffu, sq, off);
  }
  __shared__ float ss[4], sqs[4];
  if((tid & 31) == 0){ ss[tid>>5] = s; sqs[tid>>5] = sq; }
  __syncthreads();
  s  = (ss[0]+ss[1]) + (ss[2]+ss[3]);
  sq = (sqs[0]+sqs[1]) + (sqs[2]+sqs[3]);
  float mean = s * (1.f/DIM);
  float var  = sq * (1.f/DIM) - mean*mean;
  float rstd = rsqrtf(var + 1e-5f);
  float* orow = o + (long)m*DIM;
  #pragma unroll
  for(int j=0;j<4;j++){
    int d = tid + j*128;
    orow[d] = (v[j] - mean)*rstd*gw[d] + gb[d];
  }
}

// ---------------- time-shift mixes ---------------------------------------------
__global__ void mix3_k(const float* __restrict__ xn, const float* __restrict__ mk,
                       const float* __restrict__ mv, const float* __restrict__ mr){
  int g = blockIdx.x*256 + threadIdx.x;
  int t = g*2;
  int d = t & (DIM-1);
  int tok = (t >> 9) & (USEQ-1);
  float2 cur = *(const float2*)&xn[t];
  float2 sh = tok ? *(const float2*)&xn[t - DIM] : make_float2(0.f, 0.f);
  float d0 = cur.x - sh.x, d1 = cur.y - sh.y;
  uint32_t h, l;
  split2(fmaf(d0, mk[d], sh.x), fmaf(d1, mk[d+1], sh.y), h, l);
  *(uint32_t*)&g_xkh[t] = h; *(uint32_t*)&g_xkl[t] = l;
  split2(fmaf(d0, mv[d], sh.x), fmaf(d1, mv[d+1], sh.y), h, l);
  *(uint32_t*)&g_xvh[t] = h; *(uint32_t*)&g_xvl[t] = l;
  split2(fmaf(d0, mr[d], sh.x), fmaf(d1, mr[d+1], sh.y), h, l);
  *(uint32_t*)&g_xrh[t] = h; *(uint32_t*)&g_xrl[t] = l;
}
__global__ void mix2_k(const float* __restrict__ xn, const float* __restrict__ mk,
                       const float* __restrict__ mr){
  int g = blockIdx.x*256 + threadIdx.x;
  int t = g*2;
  int d = t & (DIM-1);
  int tok = (t >> 9) & (USEQ-1);
  float2 cur = *(const float2*)&xn[t];
  float2 sh = tok ? *(const float2*)&xn[t - DIM] : make_float2(0.f, 0.f);
  float d0 = cur.x - sh.x, d1 = cur.y - sh.y;
  uint32_t h, l;
  split2(fmaf(d0, mk[d], sh.x), fmaf(d1, mk[d+1], sh.y), h, l);
  *(uint32_t*)&g_xkh[t] = h; *(uint32_t*)&g_xkl[t] = l;
  split2(fmaf(d0, mr[d], sh.x), fmaf(d1, mr[d+1], sh.y), h, l);
  *(uint32_t*)&g_xrh[t] = h; *(uint32_t*)&g_xrl[t] = l;
}

// ---------------- WKV scan, pipelined, bf16 split output -----------------------
#define WG 8
__device__ __forceinline__ void wkv_load(const float* kp, const float* vp,
                                         const float* rp, long off0,
                                         float* kb, float* vb, float* rb){
  #pragma unroll
  for(int j=0;j<WG;j++){
    long off = off0 + (long)j*DIM;
    kb[j] = __ldg(kp + off); vb[j] = __ldg(vp + off); rb[j] = __ldg(rp + off);
  }
}
__device__ __forceinline__ void wkv_step(float* kb, float* vb, float* rb,
                                         bf* oh, bf* ol, long off0,
                                         float w, float u,
                                         float& aa, float& bb, float& pp){
  #pragma unroll
  for(int j=0;j<WG;j++){
    float kt = kb[j], vt = vb[j];
    float ww = u + kt;
    float p  = fmaxf(pp, ww);
    float e1 = __expf(pp - p), e2 = __expf(ww - p);
    float o  = rb[j] * (e1*aa + e2*vt) / (e1*bb + e2);
    bf h = __float2bfloat16(o);
    long off = off0 + (long)j*DIM;
    oh[off] = h;
    ol[off] = __float2bfloat16(o - __bfloat162float(h));
    float ww2 = pp + w;
    float p2  = fmaxf(ww2, kt);
    e1 = __expf(ww2 - p2); e2 = __expf(kt - p2);
    aa = e1*aa + e2*vt; bb = e1*bb + e2; pp = p2;
  }
}
__global__ void wkv_k(const float* __restrict__ k, const float* __restrict__ v,
                      const float* __restrict__ r,
                      const float* __restrict__ dec, const float* __restrict__ fir){
  int t = blockIdx.x*blockDim.x + threadIdx.x;
  int d = t & (DIM-1); int b = t >> 9;
  float w = -__expf(dec[d]);
  float u = fir[d];
  float aa = 0.f, bb = 0.f, pp = -1e38f;
  long base = (long)b*USEQ*DIM + d;
  const float* kp = k + base;
  const float* vp = v + base;
  const float* rp = r + base;
  bf* oh = g_rwh + base;
  bf* ol = g_rwl + base;
  const int NG = USEQ/WG;
  float k0b[WG], v0b[WG], r0b[WG];
  float k1b[WG], v1b[WG], r1b[WG];
  wkv_load(kp, vp, rp, 0, k0b, v0b, r0b);
  for(int g=0; g<NG; g+=2){
    long off1 = (long)(g+1)*WG*DIM;
    wkv_load(kp, vp, rp, off1, k1b, v1b, r1b);
    wkv_step(k0b, v0b, r0b, oh, ol, (long)g*WG*DIM, w, u, aa, bb, pp);
    if(g+2 < NG){
      long off2 = (long)(g+2)*WG*DIM;
      wkv_load(kp, vp, rp, off2, k0b, v0b, r0b);
    }
    wkv_step(k1b, v1b, r1b, oh, ol, off1, w, u, aa, bb, pp);
  }
}

// ---------------- olens tail ----------------------------------------------------
__global__ void tail_k(const int* __restrict__ x_len, float* __restrict__ out, int out_size){
  int b = threadIdx.x;
  if(b < BATCH && out_size >= HTOK + BATCH){
    int l1 = (x_len[b] - 1)/2 + 1;
    int ol = (l1 - 1)/2 + 1;
    out[HTOK + b] = (float)ol;
  }
}

// ---------------- host side -----------------------------------------------------
template <typename T>
static void* symaddr(const T& s){ void* p = nullptr; cudaGetSymbolAddress(&p, s); return p; }

template<int ACT, int EPI, int OUT>
static void gemm(int M, int N, int K, const bf* Ah, const bf* Al,
                 const bf* Bh, const bf* Bl, const float* bias,
                 float* C, bf* Ch, bf* Cl, const float* mul){
  cudaFuncSetAttribute(mgemm_k<ACT,EPI,OUT>, cudaFuncAttributeMaxDynamicSharedMemorySize, MSMEM);
  dim3 grid(N/128, M/128);
  mgemm_k<ACT,EPI,OUT><<<grid, 256, MSMEM>>>(M, N, K, Ah, Al, Bh, Bl, bias, C, Ch, Cl, mul);
}

extern "C" void kernel_launch(void* const* d_in, const int* in_sizes, int n_in,
                              void* d_out, int out_size){
  const float* x       = (const float*)d_in[0];
  const int*   x_len   = (const int*)  d_in[1];
  const float* conv1_w = (const float*)d_in[2];
  const float* conv1_b = (const float*)d_in[3];
  const float* conv2_w = (const float*)d_in[4];
  const float* conv2_b = (const float*)d_in[5];
  const float* conv3_w = (const float*)d_in[6];
  const float* conv3_b = (const float*)d_in[7];
  const float* embed_w = (const float*)d_in[8];
  const float* embed_b = (const float*)d_in[9];
  const float* eln_g   = (const float*)d_in[10];
  const float* eln_b   = (const float*)d_in[11];
  const float* lag     = (const float*)d_in[12];
  const float* lab     = (const float*)d_in[13];
  const float* dec     = (const float*)d_in[14];
  const float* fir     = (const float*)d_in[15];
  const float* amk     = (const float*)d_in[16];
  const float* amv     = (const float*)d_in[17];
  const float* amr     = (const float*)d_in[18];
  const float* awk     = (const float*)d_in[19];
  const float* awv     = (const float*)d_in[20];
  const float* awr     = (const float*)d_in[21];
  const float* awo     = (const float*)d_in[22];
  const float* lfg     = (const float*)d_in[23];
  const float* lfb     = (const float*)d_in[24];
  const float* fmk     = (const float*)d_in[25];
  const float* fmr     = (const float*)d_in[26];
  const float* fwk     = (const float*)d_in[27];
  const float* fwv     = (const float*)d_in[28];
  const float* fwr     = (const float*)d_in[29];
  const float* flg     = (const float*)d_in[30];
  const float* flb     = (const float*)d_in[31];
  float* out = (float*)d_out;

  bf* p_col2h = (bf*)symaddr(g_col2h); bf* p_col2l = (bf*)symaddr(g_col2l);
  bf* p_c2h   = (bf*)symaddr(g_c2h);   bf* p_c2l   = (bf*)symaddr(g_c2l);
  bf* p_col3h = (bf*)symaddr(g_col3h); bf* p_col3l = (bf*)symaddr(g_col3l);
  bf* p_c3h   = (bf*)symaddr(g_c3h);   bf* p_c3l   = (bf*)symaddr(g_c3l);
  bf* p_yrh   = (bf*)symaddr(g_yrh);   bf* p_yrl   = (bf*)symaddr(g_yrl);
  float* p_t0 = (float*)symaddr(g_t0);
  float* p_h  = (float*)symaddr(g_h);
  float* p_xn = (float*)symaddr(g_xn);
  bf* p_xkh = (bf*)symaddr(g_xkh); bf* p_xkl = (bf*)symaddr(g_xkl);
  bf* p_xvh = (bf*)symaddr(g_xvh); bf* p_xvl = (bf*)symaddr(g_xvl);
  bf* p_xrh = (bf*)symaddr(g_xrh); bf* p_xrl = (bf*)symaddr(g_xrl);
  float* p_k = (float*)symaddr(g_k);
  float* p_v = (float*)symaddr(g_v);
  float* p_r = (float*)symaddr(g_r);
  bf* p_rwh = (bf*)symaddr(g_rwh); bf* p_rwl = (bf*)symaddr(g_rwl);
  bf* p_kkh = (bf*)symaddr(g_kkh); bf* p_kkl = (bf*)symaddr(g_kkl);
  bf* p_w2Th = (bf*)symaddr(g_w2Th); bf* p_w2Tl = (bf*)symaddr(g_w2Tl);
  bf* p_w3Th = (bf*)symaddr(g_w3Th); bf* p_w3Tl = (bf*)symaddr(g_w3Tl);
  bf* p_ewTh = (bf*)symaddr(g_ewTh); bf* p_ewTl = (bf*)symaddr(g_ewTl);
  bf* p_aqkvTh = (bf*)symaddr(g_aqkvTh); bf* p_aqkvTl = (bf*)symaddr(g_aqkvTl);
  bf* p_awoTh  = (bf*)symaddr(g_awoTh);  bf* p_awoTl  = (bf*)symaddr(g_awoTl);
  bf* p_fkrTh  = (bf*)symaddr(g_fkrTh);  bf* p_fkrTl  = (bf*)symaddr(g_fkrTl);
  bf* p_fwvTh  = (bf*)symaddr(g_fwvTh);  bf* p_fwvTl  = (bf*)symaddr(g_fwvTl);

  // launches 1-6 (launch 6 = conv3 GEMM profiled by ncu -s 5 -c 1)
  prep_conv_k<<<(C2*K2C + C3*K3C + 255)/256, 256>>>(conv2_w, conv3_w);
  conv1_k<<<(BATCH*H1*W1*C1)/256, 256>>>(x, conv1_w, conv1_b);
  im2col2_k<<<(MCONV*(K2C/4))/256, 256>>>();
  gemm<1,0,1>(MCONV, C2, K2C, p_col2h, p_col2l, p_w2Th, p_w2Tl, conv2_b,
              nullptr, p_c2h, p_c2l, nullptr);
  im2col3_k<<<(MCONV*(K3C/4))/256, 256>>>();
  gemm<1,0,1>(MCONV, C3, K3C, p_col3h, p_col3l, p_w3Th, p_w3Tl, conv3_b,
              nullptr, p_c3h, p_c3l, nullptr);

  prep_big_k<<<18432, dim3(32,8)>>>(embed_w, awk, awv, awr, awo, fwr, fwk, fwv);
  reshape_k<<<MT, 256>>>();
  gemm<0,0,0>(MT, DIM, KE, p_yrh, p_yrl, p_ewTh, p_ewTl, embed_b,
              p_t0, nullptr, nullptr, nullptr);
  ln_k<<<MT, 128>>>(p_t0, eln_g, eln_b, p_h);

  // ---- RWKV blocks ----
  for(int i = 0; i < NB_; i++){
    long w2 = (long)i*DIM*DIM;
    long wh = (long)i*DIM*HID;
    long qb = (long)i*3*DIM*DIM;
    long fb = (long)i*(HID+DIM)*DIM;
    // time mixing (k/v/r use different mixed inputs -> separate GEMMs)
    ln_k<<<MT, 128>>>(p_h, lag + i*DIM, lab + i*DIM, p_xn);
    mix3_k<<<HTOK/512, 256>>>(p_xn, amk + i*DIM, amv + i*DIM, amr + i*DIM);
    gemm<0,0,0>(MT, DIM, DIM, p_xkh, p_xkl, p_aqkvTh + qb, p_aqkvTl + qb, nullptr,
                p_k, nullptr, nullptr, nullptr);
    gemm<0,0,0>(MT, DIM, DIM, p_xvh, p_xvl, p_aqkvTh + qb + (long)DIM*DIM,
                p_aqkvTl + qb + (long)DIM*DIM, nullptr,
                p_v, nullptr, nullptr, nullptr);
    gemm<2,0,0>(MT, DIM, DIM, p_xrh, p_xrl, p_aqkvTh + qb + 2L*DIM*DIM,
                p_aqkvTl + qb + 2L*DIM*DIM, nullptr,
                p_r, nullptr, nullptr, nullptr);
    wkv_k<<<(BATCH*DIM)/32, 32>>>(p_k, p_v, p_r, dec + i*DIM, fir + i*DIM);
    gemm<0,1,0>(MT, DIM, DIM, p_rwh, p_rwl, p_awoTh + w2, p_awoTl + w2, nullptr,
                p_h, nullptr, nullptr, nullptr);
    // channel mixing
    ln_k<<<MT, 128>>>(p_h, lfg + i*DIM, lfb + i*DIM, p_xn);
    mix2_k<<<HTOK/512, 256>>>(p_xn, fmk + i*DIM, fmr + i*DIM);
    gemm<3,0,1>(MT, HID, DIM, p_xkh, p_xkl, p_fkrTh + fb, p_fkrTl + fb, nullptr,
                nullptr, p_kkh, p_kkl, nullptr);
    gemm<2,0,0>(MT, DIM, DIM, p_xrh, p_xrl, p_fkrTh + fb + (long)HID*DIM,
                p_fkrTl + fb + (long)HID*DIM, nullptr,
                p_r, nullptr, nullptr, nullptr);
    gemm<0,2,0>(MT, DIM, HID, p_kkh, p_kkl, p_fwvTh + wh, p_fwvTl + wh, nullptr,
                p_h, nullptr, nullptr, p_r);
  }

  ln_k<<<MT, 128>>>(p_h, flg, flb, out);
  tail_k<<<1, 32>>>(x_len, out, out_size);
}